// round 15
// baseline (speedup 1.0000x reference)
#include <cuda_runtime.h>
#include <cuda_bf16.h>
#include <cstdint>

// ---------------- problem constants ----------------
#define E_DIM 128
#define L_DIM 256
#define H_DIM 12
#define DH_DIM 64
#define D_DIM 768          // H*DH
#define TD_DIM 2304        // 3*D
#define N_ROWS 32768       // E*L
#define LN_EPS 1e-5f

// ---------------- scratch (__device__ globals; no cudaMalloc allowed) ----------------
__device__ float g_proj[(size_t)N_ROWS * TD_DIM];          // QKV projection     (~302 MB)
__device__ float g_scores[(size_t)H_DIM * L_DIM * L_DIM];  // row scores/maps    (~3 MB)
__device__ float g_rowmask[H_DIM * L_DIM];                 // sum_e mask[h,e,j]
__device__ unsigned g_wr_hi[(size_t)TD_DIM * D_DIM];       // w_row tf32 hi
__device__ unsigned g_wr_lo[(size_t)TD_DIM * D_DIM];       // w_row tf32 lo
__device__ unsigned g_wc_hi[(size_t)TD_DIM * D_DIM];       // w_col tf32 hi
__device__ unsigned g_wc_lo[(size_t)TD_DIM * D_DIM];       // w_col tf32 lo
__device__ unsigned g_xh[(size_t)N_ROWS * D_DIM];          // LN(x) tf32 hi
__device__ unsigned g_xl[(size_t)N_ROWS * D_DIM];          // LN(x) tf32 lo

// ---------------- tf32 / async helpers ----------------
__device__ __forceinline__ unsigned f2tf32(float x) {
    unsigned u;
    asm("cvt.rna.tf32.f32 %0, %1;" : "=r"(u) : "f"(x));
    return u;
}
__device__ __forceinline__ void mma_tf32(float* d, const unsigned* a, const unsigned* b) {
    asm volatile(
        "mma.sync.aligned.m16n8k8.row.col.f32.tf32.tf32.f32 "
        "{%0,%1,%2,%3}, {%4,%5,%6,%7}, {%8,%9}, {%0,%1,%2,%3};\n"
        : "+f"(d[0]), "+f"(d[1]), "+f"(d[2]), "+f"(d[3])
        : "r"(a[0]), "r"(a[1]), "r"(a[2]), "r"(a[3]), "r"(b[0]), "r"(b[1]));
}
__device__ __forceinline__ void cp_async16(void* smem, const void* gmem) {
    unsigned saddr = (unsigned)__cvta_generic_to_shared(smem);
    asm volatile("cp.async.cg.shared.global [%0], [%1], 16;\n" :: "r"(saddr), "l"(gmem));
}
#define CP_COMMIT() asm volatile("cp.async.commit_group;\n" ::: "memory")
#define CP_WAIT0()  asm volatile("cp.async.wait_group 0;\n" ::: "memory")

__device__ __forceinline__ void split3(float x, unsigned& h, unsigned& l) {
    h = f2tf32(x);
    l = f2tf32(x - __uint_as_float(h));
}

// ---------------- reductions ----------------
__device__ __forceinline__ float warp_sum(float v) {
#pragma unroll
    for (int o = 16; o; o >>= 1) v += __shfl_xor_sync(0xffffffffu, v, o);
    return v;
}
__device__ __forceinline__ float warp_max(float v) {
#pragma unroll
    for (int o = 16; o; o >>= 1) v = fmaxf(v, __shfl_xor_sync(0xffffffffu, v, o));
    return v;
}
__device__ __forceinline__ float block_sum256(float v, float* red) {
    int lane = threadIdx.x & 31, w = threadIdx.x >> 5;
    v = warp_sum(v);
    if (lane == 0) red[w] = v;
    __syncthreads();
    if (threadIdx.x < 8) {
        float r = red[threadIdx.x];
        r += __shfl_xor_sync(0xffu, r, 4);
        r += __shfl_xor_sync(0xffu, r, 2);
        r += __shfl_xor_sync(0xffu, r, 1);
        if (threadIdx.x == 0) red[0] = r;
    }
    __syncthreads();
    float out = red[0];
    __syncthreads();
    return out;
}
__device__ __forceinline__ float block_max256(float v, float* red) {
    int lane = threadIdx.x & 31, w = threadIdx.x >> 5;
    v = warp_max(v);
    if (lane == 0) red[w] = v;
    __syncthreads();
    if (threadIdx.x < 8) {
        float r = red[threadIdx.x];
        r = fmaxf(r, __shfl_xor_sync(0xffu, r, 4));
        r = fmaxf(r, __shfl_xor_sync(0xffu, r, 2));
        r = fmaxf(r, __shfl_xor_sync(0xffu, r, 1));
        if (threadIdx.x == 0) red[0] = r;
    }
    __syncthreads();
    float out = red[0];
    __syncthreads();
    return out;
}

// ---------------- K0: split W into tf32 hi/lo ----------------
__global__ __launch_bounds__(256) void split_w_kernel(const float* __restrict__ W,
                                                      unsigned* __restrict__ hi,
                                                      unsigned* __restrict__ lo) {
    size_t i = ((size_t)blockIdx.x * 256 + threadIdx.x) * 4;
    float4 v = *(const float4*)(W + i);
    uint4 h, l;
    h.x = f2tf32(v.x); l.x = f2tf32(v.x - __uint_as_float(h.x));
    h.y = f2tf32(v.y); l.y = f2tf32(v.y - __uint_as_float(h.y));
    h.z = f2tf32(v.z); l.z = f2tf32(v.z - __uint_as_float(h.z));
    h.w = f2tf32(v.w); l.w = f2tf32(v.w - __uint_as_float(h.w));
    *(uint4*)(hi + i) = h;
    *(uint4*)(lo + i) = l;
}

// ---------------- K1/K6: LayerNorm + tf32 hi/lo split (one pass) ----------------
__global__ __launch_bounds__(256) void ln_split_kernel(const float* __restrict__ x,
                                                       const float* __restrict__ gamma,
                                                       const float* __restrict__ beta) {
    __shared__ float red[8];
    const size_t base = (size_t)blockIdx.x * D_DIM;
    const int t = threadIdx.x;
    float v0 = x[base + t];
    float v1 = x[base + t + 256];
    float v2 = x[base + t + 512];
    float s1 = block_sum256(v0 + v1 + v2, red);
    float s2 = block_sum256(v0 * v0 + v1 * v1 + v2 * v2, red);
    const float inv_d = 1.0f / (float)D_DIM;
    float mu = s1 * inv_d;
    float var = fmaxf(s2 * inv_d - mu * mu, 0.0f);
    float rs = rsqrtf(var + LN_EPS);
#pragma unroll
    for (int q = 0; q < 3; q++) {
        int idx = t + q * 256;
        float v = (q == 0) ? v0 : (q == 1) ? v1 : v2;
        float f = (v - mu) * rs * gamma[idx] + beta[idx];
        unsigned h = f2tf32(f);
        g_xh[base + idx] = h;
        g_xl[base + idx] = f2tf32(f - __uint_as_float(h));
    }
}

// ---------------- K2/K7: QKV GEMM (3xTF32, pre-split, 128x64 tile, 3 CTA/SM) -------
// C[N,2304] = LN(x)[N,768] * W[2304,768]^T + bias. Block 128(m)x64(n), warp 32x32.
#define QKV_T_STRIDE 20
#define QKV_A_TILE   (128 * QKV_T_STRIDE)         // 2560 u32
#define QKV_B_TILE   (64 * QKV_T_STRIDE)          // 1280 u32
#define QKV_SMEM_BYTES ((2 * QKV_A_TILE * 2 + 2 * QKV_B_TILE * 2) * 4)  // 61440 B
__global__ __launch_bounds__(256, 3) void qkv_gemm_tc(const unsigned* __restrict__ Ahi_g,
                                                      const unsigned* __restrict__ Alo_g,
                                                      const unsigned* __restrict__ Whi,
                                                      const unsigned* __restrict__ Wlo,
                                                      const float* __restrict__ bias) {
    extern __shared__ unsigned usm[];
    unsigned* Ash = usm;                          // [2][128][20]
    unsigned* Asl = Ash + 2 * QKV_A_TILE;
    unsigned* Bsh = Asl + 2 * QKV_A_TILE;         // [2][64][20]
    unsigned* Bsl = Bsh + 2 * QKV_B_TILE;

    const int tid = threadIdx.x;
    const int wid = tid >> 5, lane = tid & 31;
    const int warp_m = (wid >> 1) * 32;           // 0,32,64,96
    const int warp_n = (wid & 1) * 32;            // 0,32
    const int r = lane >> 2, c = lane & 3;
    const int m0 = blockIdx.y * 128;
    const int n0 = blockIdx.x * 64;

    const int rr0 = tid >> 2;                     // 0..63
    const int rr1 = rr0 + 64;                     // 64..127
    const int cc = (tid & 3) << 2;                // 0,4,8,12

    float acc[2][4][4];
#pragma unroll
    for (int t = 0; t < 2; t++)
#pragma unroll
        for (int u = 0; u < 4; u++)
#pragma unroll
            for (int v = 0; v < 4; v++) acc[t][u][v] = 0.0f;

    // ---- stage tile 0 ----
#pragma unroll
    for (int q = 0; q < 2; q++) {
        int rr = q ? rr1 : rr0;
        size_t aoff = (size_t)(m0 + rr) * D_DIM + cc;
        cp_async16(&Ash[rr * QKV_T_STRIDE + cc], Ahi_g + aoff);
        cp_async16(&Asl[rr * QKV_T_STRIDE + cc], Alo_g + aoff);
    }
    {
        size_t woff = (size_t)(n0 + rr0) * D_DIM + cc;
        cp_async16(&Bsh[rr0 * QKV_T_STRIDE + cc], Whi + woff);
        cp_async16(&Bsl[rr0 * QKV_T_STRIDE + cc], Wlo + woff);
    }
    CP_COMMIT();

    for (int kt = 0; kt < 48; kt++) {
        const int b = kt & 1;
        CP_WAIT0();
        __syncthreads();

        if (kt < 47) {
            const int k0n = (kt + 1) * 16;
            const int boA = (b ^ 1) * QKV_A_TILE;
            const int boB = (b ^ 1) * QKV_B_TILE;
#pragma unroll
            for (int q = 0; q < 2; q++) {
                int rr = q ? rr1 : rr0;
                size_t aoff = (size_t)(m0 + rr) * D_DIM + k0n + cc;
                cp_async16(&Ash[boA + rr * QKV_T_STRIDE + cc], Ahi_g + aoff);
                cp_async16(&Asl[boA + rr * QKV_T_STRIDE + cc], Alo_g + aoff);
            }
            {
                size_t woff = (size_t)(n0 + rr0) * D_DIM + k0n + cc;
                cp_async16(&Bsh[boB + rr0 * QKV_T_STRIDE + cc], Whi + woff);
                cp_async16(&Bsl[boB + rr0 * QKV_T_STRIDE + cc], Wlo + woff);
            }
            CP_COMMIT();
        }

        const unsigned* Ahb = Ash + b * QKV_A_TILE;
        const unsigned* Alb = Asl + b * QKV_A_TILE;
        const unsigned* Bhb = Bsh + b * QKV_B_TILE;
        const unsigned* Blb = Bsl + b * QKV_B_TILE;
#pragma unroll
        for (int k8 = 0; k8 < 16; k8 += 8) {
            unsigned Ahi[2][4], Alo[2][4];
#pragma unroll
            for (int t = 0; t < 2; t++) {
                int m = warp_m + t * 16 + r;
                Ahi[t][0] = Ahb[m * QKV_T_STRIDE + k8 + c];
                Ahi[t][1] = Ahb[(m + 8) * QKV_T_STRIDE + k8 + c];
                Ahi[t][2] = Ahb[m * QKV_T_STRIDE + k8 + c + 4];
                Ahi[t][3] = Ahb[(m + 8) * QKV_T_STRIDE + k8 + c + 4];
                Alo[t][0] = Alb[m * QKV_T_STRIDE + k8 + c];
                Alo[t][1] = Alb[(m + 8) * QKV_T_STRIDE + k8 + c];
                Alo[t][2] = Alb[m * QKV_T_STRIDE + k8 + c + 4];
                Alo[t][3] = Alb[(m + 8) * QKV_T_STRIDE + k8 + c + 4];
            }
#pragma unroll
            for (int u = 0; u < 4; u++) {
                int n = warp_n + u * 8 + r;
                unsigned Bh[2], Bl[2];
                Bh[0] = Bhb[n * QKV_T_STRIDE + k8 + c];
                Bh[1] = Bhb[n * QKV_T_STRIDE + k8 + 4 + c];
                Bl[0] = Blb[n * QKV_T_STRIDE + k8 + c];
                Bl[1] = Blb[n * QKV_T_STRIDE + k8 + 4 + c];
#pragma unroll
                for (int t = 0; t < 2; t++) {
                    mma_tf32(acc[t][u], Ahi[t], Bh);
                    mma_tf32(acc[t][u], Ahi[t], Bl);
                    mma_tf32(acc[t][u], Alo[t], Bh);
                }
            }
        }
    }

#pragma unroll
    for (int t = 0; t < 2; t++) {
        int row0 = m0 + warp_m + t * 16 + r;
#pragma unroll
        for (int u = 0; u < 4; u++) {
            int col = n0 + warp_n + u * 8 + c * 2;
            float2 bz = *(const float2*)(bias + col);
            float2 v0, v1;
            v0.x = acc[t][u][0] + bz.x; v0.y = acc[t][u][1] + bz.y;
            v1.x = acc[t][u][2] + bz.x; v1.y = acc[t][u][3] + bz.y;
            *(float2*)(g_proj + (size_t)row0 * TD_DIM + col) = v0;
            *(float2*)(g_proj + (size_t)(row0 + 8) * TD_DIM + col) = v1;
        }
    }
}

// ---------------- K3a: zero scores + row mask sums ----------------
__global__ __launch_bounds__(256) void scores_zero_kernel(const float* __restrict__ mask) {
    size_t idx = (size_t)blockIdx.x * 1024 + threadIdx.x * 4;
    if (idx < (size_t)H_DIM * L_DIM * L_DIM) {
        float4 z = {0.f, 0.f, 0.f, 0.f};
        *(float4*)(g_scores + idx) = z;
    }
    int t = blockIdx.x * 256 + threadIdx.x;
    if (t < H_DIM * L_DIM) {
        int h = t / L_DIM, j = t % L_DIM;
        float s = 0.0f;
        for (int e = 0; e < E_DIM; e++) s += mask[((size_t)h * E_DIM + e) * L_DIM + j];
        g_rowmask[t] = s;
    }
}

// ---------------- K3b: row scores (3xTF32, R12 ordering) -------------------------
__global__ __launch_bounds__(256, 2) void row_scores_tc() {
    __shared__ unsigned As_h[16][136], As_l[16][136];
    __shared__ unsigned Bs_h[16][136], Bs_l[16][136];
    const int tid = threadIdx.x;
    const int wid = tid >> 5, lane = tid & 31;
    const int warp_m = (wid >> 1) * 32;
    const int warp_n = (wid & 1) * 64;
    const int r = lane >> 2, c = lane & 3;
    const int it = (blockIdx.x >> 1) * 128;
    const int jt = (blockIdx.x & 1) * 128;
    const int h = blockIdx.y;
    const int e0 = blockIdx.z * 16;

    float acc[2][8][4];
#pragma unroll
    for (int t = 0; t < 2; t++)
#pragma unroll
        for (int u = 0; u < 8; u++)
#pragma unroll
            for (int v = 0; v < 4; v++) acc[t][u][v] = 0.0f;

    for (int e = e0; e < e0 + 16; e++) {
        const float* qbase = g_proj + (size_t)(e * L_DIM) * TD_DIM + h * DH_DIM;
        const float* kbase = qbase + D_DIM;
        for (int k0 = 0; k0 < DH_DIM; k0 += 16) {
#pragma unroll
            for (int q = 0; q < 2; q++) {
                int id = q * 256 + tid;
                int rr = id >> 2;
                int c4 = (id & 3) << 2;
                float4 va = *(const float4*)(qbase + (size_t)(it + rr) * TD_DIM + k0 + c4);
                unsigned hh;
                hh = f2tf32(va.x); As_h[c4 + 0][rr] = hh; As_l[c4 + 0][rr] = f2tf32(va.x - __uint_as_float(hh));
                hh = f2tf32(va.y); As_h[c4 + 1][rr] = hh; As_l[c4 + 1][rr] = f2tf32(va.y - __uint_as_float(hh));
                hh = f2tf32(va.z); As_h[c4 + 2][rr] = hh; As_l[c4 + 2][rr] = f2tf32(va.z - __uint_as_float(hh));
                hh = f2tf32(va.w); As_h[c4 + 3][rr] = hh; As_l[c4 + 3][rr] = f2tf32(va.w - __uint_as_float(hh));
                float4 vb = *(const float4*)(kbase + (size_t)(jt + rr) * TD_DIM + k0 + c4);
                hh = f2tf32(vb.x); Bs_h[c4 + 0][rr] = hh; Bs_l[c4 + 0][rr] = f2tf32(vb.x - __uint_as_float(hh));
                hh = f2tf32(vb.y); Bs_h[c4 + 1][rr] = hh; Bs_l[c4 + 1][rr] = f2tf32(vb.y - __uint_as_float(hh));
                hh = f2tf32(vb.z); Bs_h[c4 + 2][rr] = hh; Bs_l[c4 + 2][rr] = f2tf32(vb.z - __uint_as_float(hh));
                hh = f2tf32(vb.w); Bs_h[c4 + 3][rr] = hh; Bs_l[c4 + 3][rr] = f2tf32(vb.w - __uint_as_float(hh));
            }
            __syncthreads();
#pragma unroll
            for (int k8 = 0; k8 < 16; k8 += 8) {
                unsigned Ah[2][4], Al[2][4];
#pragma unroll
                for (int t = 0; t < 2; t++) {
                    int m = warp_m + t * 16 + r;
                    Ah[t][0] = As_h[k8 + c][m];     Al[t][0] = As_l[k8 + c][m];
                    Ah[t][1] = As_h[k8 + c][m + 8]; Al[t][1] = As_l[k8 + c][m + 8];
                    Ah[t][2] = As_h[k8 + c + 4][m];     Al[t][2] = As_l[k8 + c + 4][m];
                    Ah[t][3] = As_h[k8 + c + 4][m + 8]; Al[t][3] = As_l[k8 + c + 4][m + 8];
                }
#pragma unroll
                for (int u = 0; u < 8; u++) {
                    int n = warp_n + u * 8 + r;
                    unsigned Bh[2], Bl[2];
                    Bh[0] = Bs_h[k8 + c][n];     Bl[0] = Bs_l[k8 + c][n];
                    Bh[1] = Bs_h[k8 + 4 + c][n]; Bl[1] = Bs_l[k8 + 4 + c][n];
#pragma unroll
                    for (int t = 0; t < 2; t++) {
                        mma_tf32(acc[t][u], Ah[t], Bh);
                        mma_tf32(acc[t][u], Ah[t], Bl);
                        mma_tf32(acc[t][u], Al[t], Bh);
                    }
                }
            }
            __syncthreads();
        }
    }

#pragma unroll
    for (int t = 0; t < 2; t++) {
        int row = it + warp_m + t * 16 + r;
#pragma unroll
        for (int u = 0; u < 8; u++) {
            int col = jt + warp_n + u * 8 + c * 2;
            float* p0 = &g_scores[((size_t)h * L_DIM + row) * L_DIM + col];
            atomicAdd(p0, acc[t][u][0]);
            atomicAdd(p0 + 1, acc[t][u][1]);
            float* p1 = &g_scores[((size_t)h * L_DIM + row + 8) * L_DIM + col];
            atomicAdd(p1, acc[t][u][2]);
            atomicAdd(p1 + 1, acc[t][u][3]);
        }
    }
}

// ---------------- K4: softmax over j (adds row mask on the fly) ----------------
__global__ __launch_bounds__(256) void row_softmax_kernel() {
    __shared__ float red[8];
    int h = blockIdx.x / L_DIM;
    float* row = g_scores + (size_t)blockIdx.x * L_DIM;
    float v = row[threadIdx.x] + g_rowmask[h * L_DIM + threadIdx.x];
    float m = block_max256(v, red);
    float p = __expf(v - m);
    float s = block_sum256(p, red);
    row[threadIdx.x] = p / s;
}

// ---------------- K5: row AV + residual (3xTF32) -------------------
__global__ __launch_bounds__(256) void row_av_tc(const float* __restrict__ x,
                                                 float* __restrict__ out) {
    __shared__ float As[16][136];   // P^T: [j][i]
    __shared__ float Bs[16][68];    // V:   [j][c]
    const int tid = threadIdx.x;
    const int wid = tid >> 5, lane = tid & 31;
    const int warp_m = (wid >> 1) * 32;
    const int warp_n = (wid & 1) * 32;
    const int r = lane >> 2, c = lane & 3;
    const int it = blockIdx.x * 128;
    const int h = blockIdx.y;
    const int e = blockIdx.z;

    const float* pbase = g_scores + (size_t)h * L_DIM * L_DIM;
    const float* vbase = g_proj + (size_t)(e * L_DIM) * TD_DIM + 2 * D_DIM + h * DH_DIM;

    const int rr0 = tid >> 2, rr1 = rr0 + 64;
    const int cc = (tid & 3) << 2;
    const int vj = tid >> 4;
    const int vc = (tid & 15) << 2;

    float acc[2][4][4];
#pragma unroll
    for (int t = 0; t < 2; t++)
#pragma unroll
        for (int u = 0; u < 4; u++)
#pragma unroll
            for (int v = 0; v < 4; v++) acc[t][u][v] = 0.0f;

    for (int kt = 0; kt < 16; kt++) {
        const int j0 = kt * 16;
#pragma unroll
        for (int q = 0; q < 2; q++) {
            int rr = q ? rr1 : rr0;
            float4 p = *(const float4*)(pbase + (size_t)(it + rr) * L_DIM + j0 + cc);
            As[cc + 0][rr] = p.x; As[cc + 1][rr] = p.y;
            As[cc + 2][rr] = p.z; As[cc + 3][rr] = p.w;
        }
        {
            float4 v = *(const float4*)(vbase + (size_t)(j0 + vj) * TD_DIM + vc);
            *(float4*)&Bs[vj][vc] = v;
        }
        __syncthreads();
#pragma unroll
        for (int k8 = 0; k8 < 16; k8 += 8) {
            unsigned Ahi[2][4], Alo[2][4];
#pragma unroll
            for (int t = 0; t < 2; t++) {
                int m = warp_m + t * 16 + r;
                split3(As[k8 + c][m],     Ahi[t][0], Alo[t][0]);
                split3(As[k8 + c][m + 8], Ahi[t][1], Alo[t][1]);
                split3(As[k8 + c + 4][m],     Ahi[t][2], Alo[t][2]);
                split3(As[k8 + c + 4][m + 8], Ahi[t][3], Alo[t][3]);
            }
#pragma unroll
            for (int u = 0; u < 4; u++) {
                int n = warp_n + u * 8 + r;
                unsigned Bh[2], Bl[2];
                split3(Bs[k8 + c][n],     Bh[0], Bl[0]);
                split3(Bs[k8 + 4 + c][n], Bh[1], Bl[1]);
#pragma unroll
                for (int t = 0; t < 2; t++) {
                    mma_tf32(acc[t][u], Ahi[t], Bh);
                    mma_tf32(acc[t][u], Ahi[t], Bl);
                    mma_tf32(acc[t][u], Alo[t], Bh);
                }
            }
        }
        __syncthreads();
    }

#pragma unroll
    for (int t = 0; t < 2; t++) {
        int row = it + warp_m + t * 16 + r;
#pragma unroll
        for (int u = 0; u < 4; u++) {
            int col = warp_n + u * 8 + c * 2;
            size_t off0 = ((size_t)(e * L_DIM + row)) * D_DIM + h * DH_DIM + col;
            size_t off1 = ((size_t)(e * L_DIM + row + 8)) * D_DIM + h * DH_DIM + col;
            float2 x0 = *(const float2*)(x + off0);
            float2 x1 = *(const float2*)(x + off1);
            float2 v0, v1;
            v0.x = x0.x + acc[t][u][0]; v0.y = x0.y + acc[t][u][1];
            v1.x = x1.x + acc[t][u][2]; v1.y = x1.y + acc[t][u][3];
            *(float2*)(out + off0) = v0;
            *(float2*)(out + off1) = v1;
        }
    }
}

// ---------------- K8: fused column attention (3xTF32), one block per (h,l) ----
#define CK_STR 136
#define CV_STR 72
#define COL_SMEM_FLOATS (64 * CK_STR + 128 * CV_STR + 128 * CK_STR + 256)
__global__ __launch_bounds__(256) void col_attn_tc(const float* __restrict__ mask,
                                                   float* __restrict__ out) {
    extern __shared__ float sm[];
    float* Ks = sm;                         // [c][j] stride CK_STR
    float* Vs = Ks + 64 * CK_STR;           // [j][c] stride CV_STR
    float* Ss = Vs + 128 * CV_STR;          // [j][i] stride CK_STR
    float* red2 = Ss + 128 * CK_STR;
    float* Qs = Ss;                         // [c][i] alias (first 64 rows)
    const int tid = threadIdx.x;
    const int wid = tid >> 5, lane = tid & 31;
    const int r = lane >> 2, c = lane & 3;
    const int l = blockIdx.x;
    const int h = blockIdx.y;

    const float* qbase = g_proj + (size_t)l * TD_DIM + h * DH_DIM;
    const float* kbase = qbase + D_DIM;
    const float* vbase = qbase + 2 * D_DIM;

#pragma unroll
    for (int q = 0; q < 8; q++) {
        int id = q * 256 + tid;
        int rr = id & 127;
        int c4 = ((id >> 7) & 15) << 2;
        float4 va = *(const float4*)(qbase + (size_t)rr * L_DIM * TD_DIM + c4);
        Qs[(c4 + 0) * CK_STR + rr] = va.x; Qs[(c4 + 1) * CK_STR + rr] = va.y;
        Qs[(c4 + 2) * CK_STR + rr] = va.z; Qs[(c4 + 3) * CK_STR + rr] = va.w;
        float4 vb = *(const float4*)(kbase + (size_t)rr * L_DIM * TD_DIM + c4);
        Ks[(c4 + 0) * CK_STR + rr] = vb.x; Ks[(c4 + 1) * CK_STR + rr] = vb.y;
        Ks[(c4 + 2) * CK_STR + rr] = vb.z; Ks[(c4 + 3) * CK_STR + rr] = vb.w;
        int rJ = id >> 4;
        int c42 = (id & 15) << 2;
        *(float4*)&Vs[rJ * CV_STR + c42] = *(const float4*)(vbase + (size_t)rJ * L_DIM * TD_DIM + c42);
    }
    __syncthreads();

    float accS[2][8][4];
    {
        const int warp_m = (wid >> 1) * 32;
        const int warp_n = (wid & 1) * 64;
#pragma unroll
        for (int t = 0; t < 2; t++)
#pragma unroll
            for (int u = 0; u < 8; u++)
#pragma unroll
                for (int v = 0; v < 4; v++) accS[t][u][v] = 0.0f;
#pragma unroll
        for (int k8 = 0; k8 < 64; k8 += 8) {
            unsigned Ahi[2][4], Alo[2][4];
#pragma unroll
            for (int t = 0; t < 2; t++) {
                int m = warp_m + t * 16 + r;
                split3(Qs[(k8 + c) * CK_STR + m],     Ahi[t][0], Alo[t][0]);
                split3(Qs[(k8 + c) * CK_STR + m + 8], Ahi[t][1], Alo[t][1]);
                split3(Qs[(k8 + c + 4) * CK_STR + m],     Ahi[t][2], Alo[t][2]);
                split3(Qs[(k8 + c + 4) * CK_STR + m + 8], Ahi[t][3], Alo[t][3]);
            }
#pragma unroll
            for (int u = 0; u < 8; u++) {
                int n = warp_n + u * 8 + r;
                unsigned Bh[2], Bl[2];
                split3(Ks[(k8 + c) * CK_STR + n],     Bh[0], Bl[0]);
                split3(Ks[(k8 + 4 + c) * CK_STR + n], Bh[1], Bl[1]);
#pragma unroll
                for (int t = 0; t < 2; t++) {
                    mma_tf32(accS[t][u], Ahi[t], Bh);
                    mma_tf32(accS[t][u], Ahi[t], Bl);
                    mma_tf32(accS[t][u], Alo[t], Bh);
                }
            }
        }
    }
    __syncthreads();

    {
        const int warp_m = (wid >> 1) * 32;
        const int warp_n = (wid & 1) * 64;
#pragma unroll
        for (int t = 0; t < 2; t++) {
            int m = warp_m + t * 16 + r;
#pragma unroll
            for (int u = 0; u < 8; u++) {
                int j0 = warp_n + u * 8 + c * 2;
                float mk0 = mask[((size_t)h * E_DIM + j0) * L_DIM + l];
                float mk1 = mask[((size_t)h * E_DIM + j0 + 1) * L_DIM + l];
                Ss[j0 * CK_STR + m]           = accS[t][u][0] + mk0;
                Ss[(j0 + 1) * CK_STR + m]     = accS[t][u][1] + mk1;
                Ss[j0 * CK_STR + m + 8]       = accS[t][u][2] + mk0;
                Ss[(j0 + 1) * CK_STR + m + 8] = accS[t][u][3] + mk1;
            }
        }
    }
    __syncthreads();

    {
        const int i = tid & 127;
        const int half = tid >> 7;
        const int j0 = half * 64;
        float m = -3.4e38f;
#pragma unroll 8
        for (int j = 0; j < 64; j++) m = fmaxf(m, Ss[(j0 + j) * CK_STR + i]);
        red2[tid] = m;
        __syncthreads();
        m = fmaxf(red2[i], red2[i + 128]);
        float s = 0.0f;
#pragma unroll 8
        for (int j = 0; j < 64; j++) {
            float p = __expf(Ss[(j0 + j) * CK_STR + i] - m);
            Ss[(j0 + j) * CK_STR + i] = p;
            s += p;
        }
        __syncthreads();
        red2[tid] = s;
        __syncthreads();
        float inv = 1.0f / (red2[i] + red2[i + 128]);
#pragma unroll 8
        for (int j = 0; j < 64; j++) Ss[(j0 + j) * CK_STR + i] *= inv;
    }
    __syncthreads();

    {
        const int warp_m = (wid >> 1) * 32;
        const int warp_n = (wid & 1) * 32;
        float accO[2][4][4];
#pragma unroll
        for (int t = 0; t < 2; t++)
#pragma unroll
            for (int u = 0; u < 4; u++)
#pragma unroll
                for (int v = 0; v < 4; v++) accO[t][u][v] = 0.0f;
#pragma unroll
        for (int k8 = 0; k8 < 128; k8 += 8) {
            unsigned Ahi[2][4], Alo[2][4];
#pragma unroll
            for (int t = 0; t < 2; t++) {
                int m = warp_m + t * 16 + r;
                split3(Ss[(k8 + c) * CK_STR + m],     Ahi[t][0], Alo[t][0]);
                split3(Ss[(k8 + c) * CK_STR + m + 8], Ahi[t][1], Alo[t][1]);
                split3(Ss[(k8 + c + 4) * CK_STR + m],     Ahi[t][2], Alo[t][2]);
                split3(Ss[(k8 + c + 4) * CK_STR + m + 8], Ahi[t][3], Alo[t][3]);
            }
#pragma unroll
            for (int u = 0; u < 4; u++) {
                int n = warp_n + u * 8 + r;
                unsigned Bh[2], Bl[2];
                split3(Vs[(k8 + c) * CV_STR + n],     Bh[0], Bl[0]);
                split3(Vs[(k8 + 4 + c) * CV_STR + n], Bh[1], Bl[1]);
#pragma unroll
                for (int t = 0; t < 2; t++) {
                    mma_tf32(accO[t][u], Ahi[t], Bh);
                    mma_tf32(accO[t][u], Ahi[t], Bl);
                    mma_tf32(accO[t][u], Alo[t], Bh);
                }
            }
        }

#pragma unroll
        for (int t = 0; t < 2; t++) {
            int row = warp_m + t * 16 + r;
#pragma unroll
            for (int u = 0; u < 4; u++) {
                int col = warp_n + u * 8 + c * 2;
                size_t off0 = ((size_t)row * L_DIM + l) * D_DIM + h * DH_DIM + col;
                size_t off1 = ((size_t)(row + 8) * L_DIM + l) * D_DIM + h * DH_DIM + col;
                float2 c0 = *(const float2*)(out + off0);
                float2 c1 = *(const float2*)(out + off1);
                c0.x += accO[t][u][0]; c0.y += accO[t][u][1];
                c1.x += accO[t][u][2]; c1.y += accO[t][u][3];
                *(float2*)(out + off0) = c0;
                *(float2*)(out + off1) = c1;
            }
        }
    }
}

// ---------------- launcher ----------------
extern "C" void kernel_launch(void* const* d_in, const int* in_sizes, int n_in,
                              void* d_out, int out_size) {
    const float* x     = (const float*)d_in[0];
    const float* mask  = (const float*)d_in[1];
    const float* w_row = (const float*)d_in[2];
    const float* b_row = (const float*)d_in[3];
    const float* w_col = (const float*)d_in[4];
    const float* b_col = (const float*)d_in[5];
    const float* g1    = (const float*)d_in[6];
    const float* be1   = (const float*)d_in[7];
    const float* g2    = (const float*)d_in[8];
    const float* be2   = (const float*)d_in[9];
    float* out = (float*)d_out;

    unsigned *wr_hi, *wr_lo, *wc_hi, *wc_lo, *xh, *xl;
    cudaGetSymbolAddress((void**)&wr_hi, g_wr_hi);
    cudaGetSymbolAddress((void**)&wr_lo, g_wr_lo);
    cudaGetSymbolAddress((void**)&wc_hi, g_wc_hi);
    cudaGetSymbolAddress((void**)&wc_lo, g_wc_lo);
    cudaGetSymbolAddress((void**)&xh, g_xh);
    cudaGetSymbolAddress((void**)&xl, g_xl);

    const int col_smem = COL_SMEM_FLOATS * (int)sizeof(float);   // ~142 KB
    cudaFuncSetAttribute(col_attn_tc, cudaFuncAttributeMaxDynamicSharedMemorySize, col_smem);
    cudaFuncSetAttribute(qkv_gemm_tc, cudaFuncAttributeMaxDynamicSharedMemorySize, QKV_SMEM_BYTES);

    const int wsplit_blocks = (TD_DIM * D_DIM) / (256 * 4);   // 1728

    // ---- row attention stage ----
    split_w_kernel<<<wsplit_blocks, 256>>>(w_row, wr_hi, wr_lo);
    split_w_kernel<<<wsplit_blocks, 256>>>(w_col, wc_hi, wc_lo);
    ln_split_kernel<<<N_ROWS, 256>>>(x, g1, be1);
    qkv_gemm_tc<<<dim3(TD_DIM / 64, N_ROWS / 128), 256, QKV_SMEM_BYTES>>>(xh, xl, wr_hi, wr_lo, b_row);
    scores_zero_kernel<<<(H_DIM * L_DIM * L_DIM) / 1024, 256>>>(mask);
    row_scores_tc<<<dim3(4, H_DIM, 8), 256>>>();
    row_softmax_kernel<<<H_DIM * L_DIM, 256>>>();
    row_av_tc<<<dim3(2, H_DIM, E_DIM), 256>>>(x, out);   // out = x + row_out

    // ---- column attention stage ----
    ln_split_kernel<<<N_ROWS, 256>>>(out, g2, be2);
    qkv_gemm_tc<<<dim3(TD_DIM / 64, N_ROWS / 128), 256, QKV_SMEM_BYTES>>>(xh, xl, wc_hi, wc_lo, b_col);
    col_attn_tc<<<dim3(L_DIM, H_DIM), 256, col_smem>>>(mask, out);  // out += col_out
}

// round 16
// speedup vs baseline: 1.0265x; 1.0265x over previous
#include <cuda_runtime.h>
#include <cuda_bf16.h>
#include <cstdint>

// ---------------- problem constants ----------------
#define E_DIM 128
#define L_DIM 256
#define H_DIM 12
#define DH_DIM 64
#define D_DIM 768          // H*DH
#define TD_DIM 2304        // 3*D
#define N_ROWS 32768       // E*L
#define LN_EPS 1e-5f

// ---------------- scratch (__device__ globals; no cudaMalloc allowed) ----------------
__device__ float g_proj[(size_t)N_ROWS * TD_DIM];          // QKV projection     (~302 MB)
__device__ float g_scores[(size_t)H_DIM * L_DIM * L_DIM];  // row scores/maps    (~3 MB)
__device__ float g_rowmask[H_DIM * L_DIM];                 // sum_e mask[h,e,j]
__device__ unsigned g_wr_hi[(size_t)TD_DIM * D_DIM];       // w_row tf32 hi
__device__ unsigned g_wr_lo[(size_t)TD_DIM * D_DIM];       // w_row tf32 lo
__device__ unsigned g_wc_hi[(size_t)TD_DIM * D_DIM];       // w_col tf32 hi
__device__ unsigned g_wc_lo[(size_t)TD_DIM * D_DIM];       // w_col tf32 lo
__device__ unsigned g_xh[(size_t)N_ROWS * D_DIM];          // LN(x) tf32 hi
__device__ unsigned g_xl[(size_t)N_ROWS * D_DIM];          // LN(x) tf32 lo

// ---------------- tf32 / async helpers ----------------
__device__ __forceinline__ unsigned f2tf32(float x) {
    unsigned u;
    asm("cvt.rna.tf32.f32 %0, %1;" : "=r"(u) : "f"(x));
    return u;
}
__device__ __forceinline__ void mma_tf32(float* d, const unsigned* a, const unsigned* b) {
    asm volatile(
        "mma.sync.aligned.m16n8k8.row.col.f32.tf32.tf32.f32 "
        "{%0,%1,%2,%3}, {%4,%5,%6,%7}, {%8,%9}, {%0,%1,%2,%3};\n"
        : "+f"(d[0]), "+f"(d[1]), "+f"(d[2]), "+f"(d[3])
        : "r"(a[0]), "r"(a[1]), "r"(a[2]), "r"(a[3]), "r"(b[0]), "r"(b[1]));
}
__device__ __forceinline__ void cp_async16(void* smem, const void* gmem) {
    unsigned saddr = (unsigned)__cvta_generic_to_shared(smem);
    asm volatile("cp.async.cg.shared.global [%0], [%1], 16;\n" :: "r"(saddr), "l"(gmem));
}
#define CP_COMMIT() asm volatile("cp.async.commit_group;\n" ::: "memory")
#define CP_WAIT0()  asm volatile("cp.async.wait_group 0;\n" ::: "memory")
#define CP_WAIT1()  asm volatile("cp.async.wait_group 1;\n" ::: "memory")

__device__ __forceinline__ void split3(float x, unsigned& h, unsigned& l) {
    h = f2tf32(x);
    l = f2tf32(x - __uint_as_float(h));
}

// ---------------- reductions ----------------
__device__ __forceinline__ float warp_sum(float v) {
#pragma unroll
    for (int o = 16; o; o >>= 1) v += __shfl_xor_sync(0xffffffffu, v, o);
    return v;
}
__device__ __forceinline__ float warp_max(float v) {
#pragma unroll
    for (int o = 16; o; o >>= 1) v = fmaxf(v, __shfl_xor_sync(0xffffffffu, v, o));
    return v;
}
__device__ __forceinline__ float block_sum256(float v, float* red) {
    int lane = threadIdx.x & 31, w = threadIdx.x >> 5;
    v = warp_sum(v);
    if (lane == 0) red[w] = v;
    __syncthreads();
    if (threadIdx.x < 8) {
        float r = red[threadIdx.x];
        r += __shfl_xor_sync(0xffu, r, 4);
        r += __shfl_xor_sync(0xffu, r, 2);
        r += __shfl_xor_sync(0xffu, r, 1);
        if (threadIdx.x == 0) red[0] = r;
    }
    __syncthreads();
    float out = red[0];
    __syncthreads();
    return out;
}
__device__ __forceinline__ float block_max256(float v, float* red) {
    int lane = threadIdx.x & 31, w = threadIdx.x >> 5;
    v = warp_max(v);
    if (lane == 0) red[w] = v;
    __syncthreads();
    if (threadIdx.x < 8) {
        float r = red[threadIdx.x];
        r = fmaxf(r, __shfl_xor_sync(0xffu, r, 4));
        r = fmaxf(r, __shfl_xor_sync(0xffu, r, 2));
        r = fmaxf(r, __shfl_xor_sync(0xffu, r, 1));
        if (threadIdx.x == 0) red[0] = r;
    }
    __syncthreads();
    float out = red[0];
    __syncthreads();
    return out;
}

// ---------------- K0: split W into tf32 hi/lo ----------------
__global__ __launch_bounds__(256) void split_w_kernel(const float* __restrict__ W,
                                                      unsigned* __restrict__ hi,
                                                      unsigned* __restrict__ lo) {
    size_t i = ((size_t)blockIdx.x * 256 + threadIdx.x) * 4;
    float4 v = *(const float4*)(W + i);
    uint4 h, l;
    h.x = f2tf32(v.x); l.x = f2tf32(v.x - __uint_as_float(h.x));
    h.y = f2tf32(v.y); l.y = f2tf32(v.y - __uint_as_float(h.y));
    h.z = f2tf32(v.z); l.z = f2tf32(v.z - __uint_as_float(h.z));
    h.w = f2tf32(v.w); l.w = f2tf32(v.w - __uint_as_float(h.w));
    *(uint4*)(hi + i) = h;
    *(uint4*)(lo + i) = l;
}

// ---------------- K1/K6: LayerNorm + tf32 hi/lo split (one pass) ----------------
__global__ __launch_bounds__(256) void ln_split_kernel(const float* __restrict__ x,
                                                       const float* __restrict__ gamma,
                                                       const float* __restrict__ beta) {
    __shared__ float red[8];
    const size_t base = (size_t)blockIdx.x * D_DIM;
    const int t = threadIdx.x;
    float v0 = x[base + t];
    float v1 = x[base + t + 256];
    float v2 = x[base + t + 512];
    float s1 = block_sum256(v0 + v1 + v2, red);
    float s2 = block_sum256(v0 * v0 + v1 * v1 + v2 * v2, red);
    const float inv_d = 1.0f / (float)D_DIM;
    float mu = s1 * inv_d;
    float var = fmaxf(s2 * inv_d - mu * mu, 0.0f);
    float rs = rsqrtf(var + LN_EPS);
#pragma unroll
    for (int q = 0; q < 3; q++) {
        int idx = t + q * 256;
        float v = (q == 0) ? v0 : (q == 1) ? v1 : v2;
        float f = (v - mu) * rs * gamma[idx] + beta[idx];
        unsigned h = f2tf32(f);
        g_xh[base + idx] = h;
        g_xl[base + idx] = f2tf32(f - __uint_as_float(h));
    }
}

// ---------------- K2/K7: QKV GEMM (3xTF32, 256x128 tile, 512 thr, 3-stage) ---------
// C[N,2304] = LN(x)[N,768] * W[2304,768]^T + bias. Warp tile 32x64, warps 8(m)x2(n).
#define QKV_T_STRIDE 20
#define QKV_A_TILE   (256 * QKV_T_STRIDE)         // 5120 u32 per plane
#define QKV_B_TILE   (128 * QKV_T_STRIDE)         // 2560 u32 per plane
#define QKV_BUF_U32  (2 * QKV_A_TILE + 2 * QKV_B_TILE)   // 15360 u32 = 61440 B
#define QKV_SMEM_BYTES (3 * QKV_BUF_U32 * 4)      // 184320 B
__global__ __launch_bounds__(512, 1) void qkv_gemm_tc(const unsigned* __restrict__ Ahi_g,
                                                      const unsigned* __restrict__ Alo_g,
                                                      const unsigned* __restrict__ Whi,
                                                      const unsigned* __restrict__ Wlo,
                                                      const float* __restrict__ bias) {
    extern __shared__ unsigned usm[];
    // buffer layout: [Ash | Asl | Bsh | Bsl] per stage
    const int tid = threadIdx.x;
    const int wid = tid >> 5, lane = tid & 31;
    const int warp_m = (wid >> 1) * 32;           // 0..224
    const int warp_n = (wid & 1) * 64;            // 0,64
    const int r = lane >> 2, c = lane & 3;
    const int m0 = blockIdx.y * 256;
    const int n0 = blockIdx.x * 128;

    // staging coords: A rows 0..255 (2 threads/row), B rows 0..127 (4 threads/row)
    const int arow = tid >> 1;
    const int acc0 = (tid & 1) * 8;               // two float4s at acc0, acc0+4
    const int brow = tid >> 2;
    const int bcc = (tid & 3) << 2;

    float acc[2][8][4];
#pragma unroll
    for (int t = 0; t < 2; t++)
#pragma unroll
        for (int u = 0; u < 8; u++)
#pragma unroll
            for (int v = 0; v < 4; v++) acc[t][u][v] = 0.0f;

#define QKV_STAGE(buf, kc) do {                                                    \
    unsigned* Bu = usm + (buf) * QKV_BUF_U32;                                      \
    const int k0s = (kc) * 16;                                                     \
    _Pragma("unroll")                                                              \
    for (int q = 0; q < 2; q++) {                                                  \
        int ac = acc0 + q * 4;                                                     \
        size_t aoff = (size_t)(m0 + arow) * D_DIM + k0s + ac;                      \
        cp_async16(&Bu[arow * QKV_T_STRIDE + ac], Ahi_g + aoff);                   \
        cp_async16(&Bu[QKV_A_TILE + arow * QKV_T_STRIDE + ac], Alo_g + aoff);      \
    }                                                                              \
    {                                                                              \
        size_t woff = (size_t)(n0 + brow) * D_DIM + k0s + bcc;                     \
        cp_async16(&Bu[2 * QKV_A_TILE + brow * QKV_T_STRIDE + bcc], Whi + woff);   \
        cp_async16(&Bu[2 * QKV_A_TILE + QKV_B_TILE + brow * QKV_T_STRIDE + bcc],   \
                   Wlo + woff);                                                    \
    }                                                                              \
    CP_COMMIT();                                                                   \
} while (0)

    QKV_STAGE(0, 0);
    QKV_STAGE(1, 1);

    for (int kt = 0; kt < 48; kt++) {
        CP_WAIT1();          // tile kt's group complete (kt+1's may be in flight)
        __syncthreads();

        if (kt < 46) QKV_STAGE((kt + 2) % 3, kt + 2);

        const unsigned* Bu = usm + (kt % 3) * QKV_BUF_U32;
        const unsigned* Ahb = Bu;
        const unsigned* Alb = Bu + QKV_A_TILE;
        const unsigned* Bhb = Bu + 2 * QKV_A_TILE;
        const unsigned* Blb = Bhb + QKV_B_TILE;
#pragma unroll
        for (int k8 = 0; k8 < 16; k8 += 8) {
            unsigned Ahi[2][4], Alo[2][4];
#pragma unroll
            for (int t = 0; t < 2; t++) {
                int m = warp_m + t * 16 + r;
                Ahi[t][0] = Ahb[m * QKV_T_STRIDE + k8 + c];
                Ahi[t][1] = Ahb[(m + 8) * QKV_T_STRIDE + k8 + c];
                Ahi[t][2] = Ahb[m * QKV_T_STRIDE + k8 + c + 4];
                Ahi[t][3] = Ahb[(m + 8) * QKV_T_STRIDE + k8 + c + 4];
                Alo[t][0] = Alb[m * QKV_T_STRIDE + k8 + c];
                Alo[t][1] = Alb[(m + 8) * QKV_T_STRIDE + k8 + c];
                Alo[t][2] = Alb[m * QKV_T_STRIDE + k8 + c + 4];
                Alo[t][3] = Alb[(m + 8) * QKV_T_STRIDE + k8 + c + 4];
            }
#pragma unroll
            for (int u = 0; u < 8; u++) {
                int n = warp_n + u * 8 + r;
                unsigned Bh[2], Bl[2];
                Bh[0] = Bhb[n * QKV_T_STRIDE + k8 + c];
                Bh[1] = Bhb[n * QKV_T_STRIDE + k8 + 4 + c];
                Bl[0] = Blb[n * QKV_T_STRIDE + k8 + c];
                Bl[1] = Blb[n * QKV_T_STRIDE + k8 + 4 + c];
#pragma unroll
                for (int t = 0; t < 2; t++) {
                    mma_tf32(acc[t][u], Ahi[t], Bh);
                    mma_tf32(acc[t][u], Ahi[t], Bl);
                    mma_tf32(acc[t][u], Alo[t], Bh);
                }
            }
        }
    }

#pragma unroll
    for (int t = 0; t < 2; t++) {
        int row0 = m0 + warp_m + t * 16 + r;
#pragma unroll
        for (int u = 0; u < 8; u++) {
            int col = n0 + warp_n + u * 8 + c * 2;
            float2 bz = *(const float2*)(bias + col);
            float2 v0, v1;
            v0.x = acc[t][u][0] + bz.x; v0.y = acc[t][u][1] + bz.y;
            v1.x = acc[t][u][2] + bz.x; v1.y = acc[t][u][3] + bz.y;
            *(float2*)(g_proj + (size_t)row0 * TD_DIM + col) = v0;
            *(float2*)(g_proj + (size_t)(row0 + 8) * TD_DIM + col) = v1;
        }
    }
}

// ---------------- K3a: zero scores + row mask sums ----------------
__global__ __launch_bounds__(256) void scores_zero_kernel(const float* __restrict__ mask) {
    size_t idx = (size_t)blockIdx.x * 1024 + threadIdx.x * 4;
    if (idx < (size_t)H_DIM * L_DIM * L_DIM) {
        float4 z = {0.f, 0.f, 0.f, 0.f};
        *(float4*)(g_scores + idx) = z;
    }
    int t = blockIdx.x * 256 + threadIdx.x;
    if (t < H_DIM * L_DIM) {
        int h = t / L_DIM, j = t % L_DIM;
        float s = 0.0f;
        for (int e = 0; e < E_DIM; e++) s += mask[((size_t)h * E_DIM + e) * L_DIM + j];
        g_rowmask[t] = s;
    }
}

// ---------------- K3b: row scores (3xTF32, R12 ordering) -------------------------
__global__ __launch_bounds__(256, 2) void row_scores_tc() {
    __shared__ unsigned As_h[16][136], As_l[16][136];
    __shared__ unsigned Bs_h[16][136], Bs_l[16][136];
    const int tid = threadIdx.x;
    const int wid = tid >> 5, lane = tid & 31;
    const int warp_m = (wid >> 1) * 32;
    const int warp_n = (wid & 1) * 64;
    const int r = lane >> 2, c = lane & 3;
    const int it = (blockIdx.x >> 1) * 128;
    const int jt = (blockIdx.x & 1) * 128;
    const int h = blockIdx.y;
    const int e0 = blockIdx.z * 16;

    float acc[2][8][4];
#pragma unroll
    for (int t = 0; t < 2; t++)
#pragma unroll
        for (int u = 0; u < 8; u++)
#pragma unroll
            for (int v = 0; v < 4; v++) acc[t][u][v] = 0.0f;

    for (int e = e0; e < e0 + 16; e++) {
        const float* qbase = g_proj + (size_t)(e * L_DIM) * TD_DIM + h * DH_DIM;
        const float* kbase = qbase + D_DIM;
        for (int k0 = 0; k0 < DH_DIM; k0 += 16) {
#pragma unroll
            for (int q = 0; q < 2; q++) {
                int id = q * 256 + tid;
                int rr = id >> 2;
                int c4 = (id & 3) << 2;
                float4 va = *(const float4*)(qbase + (size_t)(it + rr) * TD_DIM + k0 + c4);
                unsigned hh;
                hh = f2tf32(va.x); As_h[c4 + 0][rr] = hh; As_l[c4 + 0][rr] = f2tf32(va.x - __uint_as_float(hh));
                hh = f2tf32(va.y); As_h[c4 + 1][rr] = hh; As_l[c4 + 1][rr] = f2tf32(va.y - __uint_as_float(hh));
                hh = f2tf32(va.z); As_h[c4 + 2][rr] = hh; As_l[c4 + 2][rr] = f2tf32(va.z - __uint_as_float(hh));
                hh = f2tf32(va.w); As_h[c4 + 3][rr] = hh; As_l[c4 + 3][rr] = f2tf32(va.w - __uint_as_float(hh));
                float4 vb = *(const float4*)(kbase + (size_t)(jt + rr) * TD_DIM + k0 + c4);
                hh = f2tf32(vb.x); Bs_h[c4 + 0][rr] = hh; Bs_l[c4 + 0][rr] = f2tf32(vb.x - __uint_as_float(hh));
                hh = f2tf32(vb.y); Bs_h[c4 + 1][rr] = hh; Bs_l[c4 + 1][rr] = f2tf32(vb.y - __uint_as_float(hh));
                hh = f2tf32(vb.z); Bs_h[c4 + 2][rr] = hh; Bs_l[c4 + 2][rr] = f2tf32(vb.z - __uint_as_float(hh));
                hh = f2tf32(vb.w); Bs_h[c4 + 3][rr] = hh; Bs_l[c4 + 3][rr] = f2tf32(vb.w - __uint_as_float(hh));
            }
            __syncthreads();
#pragma unroll
            for (int k8 = 0; k8 < 16; k8 += 8) {
                unsigned Ah[2][4], Al[2][4];
#pragma unroll
                for (int t = 0; t < 2; t++) {
                    int m = warp_m + t * 16 + r;
                    Ah[t][0] = As_h[k8 + c][m];     Al[t][0] = As_l[k8 + c][m];
                    Ah[t][1] = As_h[k8 + c][m + 8]; Al[t][1] = As_l[k8 + c][m + 8];
                    Ah[t][2] = As_h[k8 + c + 4][m];     Al[t][2] = As_l[k8 + c + 4][m];
                    Ah[t][3] = As_h[k8 + c + 4][m + 8]; Al[t][3] = As_l[k8 + c + 4][m + 8];
                }
#pragma unroll
                for (int u = 0; u < 8; u++) {
                    int n = warp_n + u * 8 + r;
                    unsigned Bh[2], Bl[2];
                    Bh[0] = Bs_h[k8 + c][n];     Bl[0] = Bs_l[k8 + c][n];
                    Bh[1] = Bs_h[k8 + 4 + c][n]; Bl[1] = Bs_l[k8 + 4 + c][n];
#pragma unroll
                    for (int t = 0; t < 2; t++) {
                        mma_tf32(acc[t][u], Ah[t], Bh);
                        mma_tf32(acc[t][u], Ah[t], Bl);
                        mma_tf32(acc[t][u], Al[t], Bh);
                    }
                }
            }
            __syncthreads();
        }
    }

#pragma unroll
    for (int t = 0; t < 2; t++) {
        int row = it + warp_m + t * 16 + r;
#pragma unroll
        for (int u = 0; u < 8; u++) {
            int col = jt + warp_n + u * 8 + c * 2;
            float* p0 = &g_scores[((size_t)h * L_DIM + row) * L_DIM + col];
            atomicAdd(p0, acc[t][u][0]);
            atomicAdd(p0 + 1, acc[t][u][1]);
            float* p1 = &g_scores[((size_t)h * L_DIM + row + 8) * L_DIM + col];
            atomicAdd(p1, acc[t][u][2]);
            atomicAdd(p1 + 1, acc[t][u][3]);
        }
    }
}

// ---------------- K4: softmax over j (adds row mask on the fly) ----------------
__global__ __launch_bounds__(256) void row_softmax_kernel() {
    __shared__ float red[8];
    int h = blockIdx.x / L_DIM;
    float* row = g_scores + (size_t)blockIdx.x * L_DIM;
    float v = row[threadIdx.x] + g_rowmask[h * L_DIM + threadIdx.x];
    float m = block_max256(v, red);
    float p = __expf(v - m);
    float s = block_sum256(p, red);
    row[threadIdx.x] = p / s;
}

// ---------------- K5: row AV + residual (3xTF32) -------------------
__global__ __launch_bounds__(256) void row_av_tc(const float* __restrict__ x,
                                                 float* __restrict__ out) {
    __shared__ float As[16][136];   // P^T: [j][i]
    __shared__ float Bs[16][68];    // V:   [j][c]
    const int tid = threadIdx.x;
    const int wid = tid >> 5, lane = tid & 31;
    const int warp_m = (wid >> 1) * 32;
    const int warp_n = (wid & 1) * 32;
    const int r = lane >> 2, c = lane & 3;
    const int it = blockIdx.x * 128;
    const int h = blockIdx.y;
    const int e = blockIdx.z;

    const float* pbase = g_scores + (size_t)h * L_DIM * L_DIM;
    const float* vbase = g_proj + (size_t)(e * L_DIM) * TD_DIM + 2 * D_DIM + h * DH_DIM;

    const int rr0 = tid >> 2, rr1 = rr0 + 64;
    const int cc = (tid & 3) << 2;
    const int vj = tid >> 4;
    const int vc = (tid & 15) << 2;

    float acc[2][4][4];
#pragma unroll
    for (int t = 0; t < 2; t++)
#pragma unroll
        for (int u = 0; u < 4; u++)
#pragma unroll
            for (int v = 0; v < 4; v++) acc[t][u][v] = 0.0f;

    for (int kt = 0; kt < 16; kt++) {
        const int j0 = kt * 16;
#pragma unroll
        for (int q = 0; q < 2; q++) {
            int rr = q ? rr1 : rr0;
            float4 p = *(const float4*)(pbase + (size_t)(it + rr) * L_DIM + j0 + cc);
            As[cc + 0][rr] = p.x; As[cc + 1][rr] = p.y;
            As[cc + 2][rr] = p.z; As[cc + 3][rr] = p.w;
        }
        {
            float4 v = *(const float4*)(vbase + (size_t)(j0 + vj) * TD_DIM + vc);
            *(float4*)&Bs[vj][vc] = v;
        }
        __syncthreads();
#pragma unroll
        for (int k8 = 0; k8 < 16; k8 += 8) {
            unsigned Ahi[2][4], Alo[2][4];
#pragma unroll
            for (int t = 0; t < 2; t++) {
                int m = warp_m + t * 16 + r;
                split3(As[k8 + c][m],     Ahi[t][0], Alo[t][0]);
                split3(As[k8 + c][m + 8], Ahi[t][1], Alo[t][1]);
                split3(As[k8 + c + 4][m],     Ahi[t][2], Alo[t][2]);
                split3(As[k8 + c + 4][m + 8], Ahi[t][3], Alo[t][3]);
            }
#pragma unroll
            for (int u = 0; u < 4; u++) {
                int n = warp_n + u * 8 + r;
                unsigned Bh[2], Bl[2];
                split3(Bs[k8 + c][n],     Bh[0], Bl[0]);
                split3(Bs[k8 + 4 + c][n], Bh[1], Bl[1]);
#pragma unroll
                for (int t = 0; t < 2; t++) {
                    mma_tf32(acc[t][u], Ahi[t], Bh);
                    mma_tf32(acc[t][u], Ahi[t], Bl);
                    mma_tf32(acc[t][u], Alo[t], Bh);
                }
            }
        }
        __syncthreads();
    }

#pragma unroll
    for (int t = 0; t < 2; t++) {
        int row = it + warp_m + t * 16 + r;
#pragma unroll
        for (int u = 0; u < 4; u++) {
            int col = warp_n + u * 8 + c * 2;
            size_t off0 = ((size_t)(e * L_DIM + row)) * D_DIM + h * DH_DIM + col;
            size_t off1 = ((size_t)(e * L_DIM + row + 8)) * D_DIM + h * DH_DIM + col;
            float2 x0 = *(const float2*)(x + off0);
            float2 x1 = *(const float2*)(x + off1);
            float2 v0, v1;
            v0.x = x0.x + acc[t][u][0]; v0.y = x0.y + acc[t][u][1];
            v1.x = x1.x + acc[t][u][2]; v1.y = x1.y + acc[t][u][3];
            *(float2*)(out + off0) = v0;
            *(float2*)(out + off1) = v1;
        }
    }
}

// ---------------- K8: fused column attention (3xTF32), one block per (h,l) ----
#define CK_STR 136
#define CV_STR 72
#define COL_SMEM_FLOATS (64 * CK_STR + 128 * CV_STR + 128 * CK_STR + 256)
__global__ __launch_bounds__(256) void col_attn_tc(const float* __restrict__ mask,
                                                   float* __restrict__ out) {
    extern __shared__ float sm[];
    float* Ks = sm;                         // [c][j] stride CK_STR
    float* Vs = Ks + 64 * CK_STR;           // [j][c] stride CV_STR
    float* Ss = Vs + 128 * CV_STR;          // [j][i] stride CK_STR
    float* red2 = Ss + 128 * CK_STR;
    float* Qs = Ss;                         // [c][i] alias (first 64 rows)
    const int tid = threadIdx.x;
    const int wid = tid >> 5, lane = tid & 31;
    const int r = lane >> 2, c = lane & 3;
    const int l = blockIdx.x;
    const int h = blockIdx.y;

    const float* qbase = g_proj + (size_t)l * TD_DIM + h * DH_DIM;
    const float* kbase = qbase + D_DIM;
    const float* vbase = qbase + 2 * D_DIM;

#pragma unroll
    for (int q = 0; q < 8; q++) {
        int id = q * 256 + tid;
        int rr = id & 127;
        int c4 = ((id >> 7) & 15) << 2;
        float4 va = *(const float4*)(qbase + (size_t)rr * L_DIM * TD_DIM + c4);
        Qs[(c4 + 0) * CK_STR + rr] = va.x; Qs[(c4 + 1) * CK_STR + rr] = va.y;
        Qs[(c4 + 2) * CK_STR + rr] = va.z; Qs[(c4 + 3) * CK_STR + rr] = va.w;
        float4 vb = *(const float4*)(kbase + (size_t)rr * L_DIM * TD_DIM + c4);
        Ks[(c4 + 0) * CK_STR + rr] = vb.x; Ks[(c4 + 1) * CK_STR + rr] = vb.y;
        Ks[(c4 + 2) * CK_STR + rr] = vb.z; Ks[(c4 + 3) * CK_STR + rr] = vb.w;
        int rJ = id >> 4;
        int c42 = (id & 15) << 2;
        *(float4*)&Vs[rJ * CV_STR + c42] = *(const float4*)(vbase + (size_t)rJ * L_DIM * TD_DIM + c42);
    }
    __syncthreads();

    float accS[2][8][4];
    {
        const int warp_m = (wid >> 1) * 32;
        const int warp_n = (wid & 1) * 64;
#pragma unroll
        for (int t = 0; t < 2; t++)
#pragma unroll
            for (int u = 0; u < 8; u++)
#pragma unroll
                for (int v = 0; v < 4; v++) accS[t][u][v] = 0.0f;
#pragma unroll
        for (int k8 = 0; k8 < 64; k8 += 8) {
            unsigned Ahi[2][4], Alo[2][4];
#pragma unroll
            for (int t = 0; t < 2; t++) {
                int m = warp_m + t * 16 + r;
                split3(Qs[(k8 + c) * CK_STR + m],     Ahi[t][0], Alo[t][0]);
                split3(Qs[(k8 + c) * CK_STR + m + 8], Ahi[t][1], Alo[t][1]);
                split3(Qs[(k8 + c + 4) * CK_STR + m],     Ahi[t][2], Alo[t][2]);
                split3(Qs[(k8 + c + 4) * CK_STR + m + 8], Ahi[t][3], Alo[t][3]);
            }
#pragma unroll
            for (int u = 0; u < 8; u++) {
                int n = warp_n + u * 8 + r;
                unsigned Bh[2], Bl[2];
                split3(Ks[(k8 + c) * CK_STR + n],     Bh[0], Bl[0]);
                split3(Ks[(k8 + 4 + c) * CK_STR + n], Bh[1], Bl[1]);
#pragma unroll
                for (int t = 0; t < 2; t++) {
                    mma_tf32(accS[t][u], Ahi[t], Bh);
                    mma_tf32(accS[t][u], Ahi[t], Bl);
                    mma_tf32(accS[t][u], Alo[t], Bh);
                }
            }
        }
    }
    __syncthreads();

    {
        const int warp_m = (wid >> 1) * 32;
        const int warp_n = (wid & 1) * 64;
#pragma unroll
        for (int t = 0; t < 2; t++) {
            int m = warp_m + t * 16 + r;
#pragma unroll
            for (int u = 0; u < 8; u++) {
                int j0 = warp_n + u * 8 + c * 2;
                float mk0 = mask[((size_t)h * E_DIM + j0) * L_DIM + l];
                float mk1 = mask[((size_t)h * E_DIM + j0 + 1) * L_DIM + l];
                Ss[j0 * CK_STR + m]           = accS[t][u][0] + mk0;
                Ss[(j0 + 1) * CK_STR + m]     = accS[t][u][1] + mk1;
                Ss[j0 * CK_STR + m + 8]       = accS[t][u][2] + mk0;
                Ss[(j0 + 1) * CK_STR + m + 8] = accS[t][u][3] + mk1;
            }
        }
    }
    __syncthreads();

    {
        const int i = tid & 127;
        const int half = tid >> 7;
        const int j0 = half * 64;
        float m = -3.4e38f;
#pragma unroll 8
        for (int j = 0; j < 64; j++) m = fmaxf(m, Ss[(j0 + j) * CK_STR + i]);
        red2[tid] = m;
        __syncthreads();
        m = fmaxf(red2[i], red2[i + 128]);
        float s = 0.0f;
#pragma unroll 8
        for (int j = 0; j < 64; j++) {
            float p = __expf(Ss[(j0 + j) * CK_STR + i] - m);
            Ss[(j0 + j) * CK_STR + i] = p;
            s += p;
        }
        __syncthreads();
        red2[tid] = s;
        __syncthreads();
        float inv = 1.0f / (red2[i] + red2[i + 128]);
#pragma unroll 8
        for (int j = 0; j < 64; j++) Ss[(j0 + j) * CK_STR + i] *= inv;
    }
    __syncthreads();

    {
        const int warp_m = (wid >> 1) * 32;
        const int warp_n = (wid & 1) * 32;
        float accO[2][4][4];
#pragma unroll
        for (int t = 0; t < 2; t++)
#pragma unroll
            for (int u = 0; u < 4; u++)
#pragma unroll
                for (int v = 0; v < 4; v++) accO[t][u][v] = 0.0f;
#pragma unroll
        for (int k8 = 0; k8 < 128; k8 += 8) {
            unsigned Ahi[2][4], Alo[2][4];
#pragma unroll
            for (int t = 0; t < 2; t++) {
                int m = warp_m + t * 16 + r;
                split3(Ss[(k8 + c) * CK_STR + m],     Ahi[t][0], Alo[t][0]);
                split3(Ss[(k8 + c) * CK_STR + m + 8], Ahi[t][1], Alo[t][1]);
                split3(Ss[(k8 + c + 4) * CK_STR + m],     Ahi[t][2], Alo[t][2]);
                split3(Ss[(k8 + c + 4) * CK_STR + m + 8], Ahi[t][3], Alo[t][3]);
            }
#pragma unroll
            for (int u = 0; u < 4; u++) {
                int n = warp_n + u * 8 + r;
                unsigned Bh[2], Bl[2];
                split3(Vs[(k8 + c) * CV_STR + n],     Bh[0], Bl[0]);
                split3(Vs[(k8 + 4 + c) * CV_STR + n], Bh[1], Bl[1]);
#pragma unroll
                for (int t = 0; t < 2; t++) {
                    mma_tf32(accO[t][u], Ahi[t], Bh);
                    mma_tf32(accO[t][u], Ahi[t], Bl);
                    mma_tf32(accO[t][u], Alo[t], Bh);
                }
            }
        }

#pragma unroll
        for (int t = 0; t < 2; t++) {
            int row = warp_m + t * 16 + r;
#pragma unroll
            for (int u = 0; u < 4; u++) {
                int col = warp_n + u * 8 + c * 2;
                size_t off0 = ((size_t)row * L_DIM + l) * D_DIM + h * DH_DIM + col;
                size_t off1 = ((size_t)(row + 8) * L_DIM + l) * D_DIM + h * DH_DIM + col;
                float2 c0 = *(const float2*)(out + off0);
                float2 c1 = *(const float2*)(out + off1);
                c0.x += accO[t][u][0]; c0.y += accO[t][u][1];
                c1.x += accO[t][u][2]; c1.y += accO[t][u][3];
                *(float2*)(out + off0) = c0;
                *(float2*)(out + off1) = c1;
            }
        }
    }
}

// ---------------- launcher ----------------
extern "C" void kernel_launch(void* const* d_in, const int* in_sizes, int n_in,
                              void* d_out, int out_size) {
    const float* x     = (const float*)d_in[0];
    const float* mask  = (const float*)d_in[1];
    const float* w_row = (const float*)d_in[2];
    const float* b_row = (const float*)d_in[3];
    const float* w_col = (const float*)d_in[4];
    const float* b_col = (const float*)d_in[5];
    const float* g1    = (const float*)d_in[6];
    const float* be1   = (const float*)d_in[7];
    const float* g2    = (const float*)d_in[8];
    const float* be2   = (const float*)d_in[9];
    float* out = (float*)d_out;

    unsigned *wr_hi, *wr_lo, *wc_hi, *wc_lo, *xh, *xl;
    cudaGetSymbolAddress((void**)&wr_hi, g_wr_hi);
    cudaGetSymbolAddress((void**)&wr_lo, g_wr_lo);
    cudaGetSymbolAddress((void**)&wc_hi, g_wc_hi);
    cudaGetSymbolAddress((void**)&wc_lo, g_wc_lo);
    cudaGetSymbolAddress((void**)&xh, g_xh);
    cudaGetSymbolAddress((void**)&xl, g_xl);

    const int col_smem = COL_SMEM_FLOATS * (int)sizeof(float);   // ~142 KB
    cudaFuncSetAttribute(col_attn_tc, cudaFuncAttributeMaxDynamicSharedMemorySize, col_smem);
    cudaFuncSetAttribute(qkv_gemm_tc, cudaFuncAttributeMaxDynamicSharedMemorySize, QKV_SMEM_BYTES);

    const int wsplit_blocks = (TD_DIM * D_DIM) / (256 * 4);   // 1728

    // ---- row attention stage ----
    split_w_kernel<<<wsplit_blocks, 256>>>(w_row, wr_hi, wr_lo);
    split_w_kernel<<<wsplit_blocks, 256>>>(w_col, wc_hi, wc_lo);
    ln_split_kernel<<<N_ROWS, 256>>>(x, g1, be1);
    qkv_gemm_tc<<<dim3(TD_DIM / 128, N_ROWS / 256), 512, QKV_SMEM_BYTES>>>(xh, xl, wr_hi, wr_lo, b_row);
    scores_zero_kernel<<<(H_DIM * L_DIM * L_DIM) / 1024, 256>>>(mask);
    row_scores_tc<<<dim3(4, H_DIM, 8), 256>>>();
    row_softmax_kernel<<<H_DIM * L_DIM, 256>>>();
    row_av_tc<<<dim3(2, H_DIM, E_DIM), 256>>>(x, out);   // out = x + row_out

    // ---- column attention stage ----
    ln_split_kernel<<<N_ROWS, 256>>>(out, g2, be2);
    qkv_gemm_tc<<<dim3(TD_DIM / 128, N_ROWS / 256), 512, QKV_SMEM_BYTES>>>(xh, xl, wc_hi, wc_lo, b_col);
    col_attn_tc<<<dim3(L_DIM, H_DIM), 256, col_smem>>>(mask, out);  // out += col_out
}

// round 17
// speedup vs baseline: 1.1133x; 1.0845x over previous
#include <cuda_runtime.h>
#include <cuda_bf16.h>
#include <cstdint>

// ---------------- problem constants ----------------
#define E_DIM 128
#define L_DIM 256
#define H_DIM 12
#define DH_DIM 64
#define D_DIM 768          // H*DH
#define TD_DIM 2304        // 3*D
#define N_ROWS 32768       // E*L
#define LN_EPS 1e-5f

// ---------------- scratch (__device__ globals; no cudaMalloc allowed) ----------------
__device__ float g_proj[(size_t)N_ROWS * TD_DIM];          // QKV projection     (~302 MB)
__device__ float g_scores[(size_t)H_DIM * L_DIM * L_DIM];  // row scores/maps    (~3 MB)
__device__ float g_rowmask[H_DIM * L_DIM];                 // sum_e mask[h,e,j]
__device__ unsigned g_wr_hi[(size_t)TD_DIM * D_DIM];       // w_row tf32 hi
__device__ unsigned g_wr_lo[(size_t)TD_DIM * D_DIM];       // w_row tf32 lo
__device__ unsigned g_wc_hi[(size_t)TD_DIM * D_DIM];       // w_col tf32 hi
__device__ unsigned g_wc_lo[(size_t)TD_DIM * D_DIM];       // w_col tf32 lo
__device__ unsigned g_xh[(size_t)N_ROWS * D_DIM];          // LN(x) tf32 hi
__device__ unsigned g_xl[(size_t)N_ROWS * D_DIM];          // LN(x) tf32 lo

// ---------------- tf32 / async helpers ----------------
__device__ __forceinline__ unsigned f2tf32(float x) {
    unsigned u;
    asm("cvt.rna.tf32.f32 %0, %1;" : "=r"(u) : "f"(x));
    return u;
}
__device__ __forceinline__ void mma_tf32(float* d, const unsigned* a, const unsigned* b) {
    asm volatile(
        "mma.sync.aligned.m16n8k8.row.col.f32.tf32.tf32.f32 "
        "{%0,%1,%2,%3}, {%4,%5,%6,%7}, {%8,%9}, {%0,%1,%2,%3};\n"
        : "+f"(d[0]), "+f"(d[1]), "+f"(d[2]), "+f"(d[3])
        : "r"(a[0]), "r"(a[1]), "r"(a[2]), "r"(a[3]), "r"(b[0]), "r"(b[1]));
}
__device__ __forceinline__ void cp_async16(void* smem, const void* gmem) {
    unsigned saddr = (unsigned)__cvta_generic_to_shared(smem);
    asm volatile("cp.async.cg.shared.global [%0], [%1], 16;\n" :: "r"(saddr), "l"(gmem));
}
#define CP_COMMIT() asm volatile("cp.async.commit_group;\n" ::: "memory")
#define CP_WAIT0()  asm volatile("cp.async.wait_group 0;\n" ::: "memory")

__device__ __forceinline__ void split3(float x, unsigned& h, unsigned& l) {
    h = f2tf32(x);
    l = f2tf32(x - __uint_as_float(h));
}

// ---------------- reductions ----------------
__device__ __forceinline__ float warp_sum(float v) {
#pragma unroll
    for (int o = 16; o; o >>= 1) v += __shfl_xor_sync(0xffffffffu, v, o);
    return v;
}
__device__ __forceinline__ float warp_max(float v) {
#pragma unroll
    for (int o = 16; o; o >>= 1) v = fmaxf(v, __shfl_xor_sync(0xffffffffu, v, o));
    return v;
}
__device__ __forceinline__ float block_sum256(float v, float* red) {
    int lane = threadIdx.x & 31, w = threadIdx.x >> 5;
    v = warp_sum(v);
    if (lane == 0) red[w] = v;
    __syncthreads();
    if (threadIdx.x < 8) {
        float r = red[threadIdx.x];
        r += __shfl_xor_sync(0xffu, r, 4);
        r += __shfl_xor_sync(0xffu, r, 2);
        r += __shfl_xor_sync(0xffu, r, 1);
        if (threadIdx.x == 0) red[0] = r;
    }
    __syncthreads();
    float out = red[0];
    __syncthreads();
    return out;
}
__device__ __forceinline__ float block_max256(float v, float* red) {
    int lane = threadIdx.x & 31, w = threadIdx.x >> 5;
    v = warp_max(v);
    if (lane == 0) red[w] = v;
    __syncthreads();
    if (threadIdx.x < 8) {
        float r = red[threadIdx.x];
        r = fmaxf(r, __shfl_xor_sync(0xffu, r, 4));
        r = fmaxf(r, __shfl_xor_sync(0xffu, r, 2));
        r = fmaxf(r, __shfl_xor_sync(0xffu, r, 1));
        if (threadIdx.x == 0) red[0] = r;
    }
    __syncthreads();
    float out = red[0];
    __syncthreads();
    return out;
}

// ---------------- K0: split W into tf32 hi/lo ----------------
__global__ __launch_bounds__(256) void split_w_kernel(const float* __restrict__ W,
                                                      unsigned* __restrict__ hi,
                                                      unsigned* __restrict__ lo) {
    size_t i = ((size_t)blockIdx.x * 256 + threadIdx.x) * 4;
    float4 v = *(const float4*)(W + i);
    uint4 h, l;
    h.x = f2tf32(v.x); l.x = f2tf32(v.x - __uint_as_float(h.x));
    h.y = f2tf32(v.y); l.y = f2tf32(v.y - __uint_as_float(h.y));
    h.z = f2tf32(v.z); l.z = f2tf32(v.z - __uint_as_float(h.z));
    h.w = f2tf32(v.w); l.w = f2tf32(v.w - __uint_as_float(h.w));
    *(uint4*)(hi + i) = h;
    *(uint4*)(lo + i) = l;
}

// ---------------- K1/K6: LayerNorm + tf32 hi/lo split (one pass) ----------------
__global__ __launch_bounds__(256) void ln_split_kernel(const float* __restrict__ x,
                                                       const float* __restrict__ gamma,
                                                       const float* __restrict__ beta) {
    __shared__ float red[8];
    const size_t base = (size_t)blockIdx.x * D_DIM;
    const int t = threadIdx.x;
    float v0 = x[base + t];
    float v1 = x[base + t + 256];
    float v2 = x[base + t + 512];
    float s1 = block_sum256(v0 + v1 + v2, red);
    float s2 = block_sum256(v0 * v0 + v1 * v1 + v2 * v2, red);
    const float inv_d = 1.0f / (float)D_DIM;
    float mu = s1 * inv_d;
    float var = fmaxf(s2 * inv_d - mu * mu, 0.0f);
    float rs = rsqrtf(var + LN_EPS);
#pragma unroll
    for (int q = 0; q < 3; q++) {
        int idx = t + q * 256;
        float v = (q == 0) ? v0 : (q == 1) ? v1 : v2;
        float f = (v - mu) * rs * gamma[idx] + beta[idx];
        unsigned h = f2tf32(f);
        g_xh[base + idx] = h;
        g_xl[base + idx] = f2tf32(f - __uint_as_float(h));
    }
}

// ---------------- K2/K7: QKV GEMM (3xTF32, pre-split operands, pipelined) ----------
// R12 configuration: block 128x128, warp 32x64, 2 CTA/SM, double buffer.
#define QKV_T_STRIDE 20
#define QKV_T_TILE   (128 * QKV_T_STRIDE)         // 2560 u32 per tile
#define QKV_SMEM_BYTES (8 * QKV_T_TILE * 4)       // 81920 B
__global__ __launch_bounds__(256, 2) void qkv_gemm_tc(const unsigned* __restrict__ Ahi_g,
                                                      const unsigned* __restrict__ Alo_g,
                                                      const unsigned* __restrict__ Whi,
                                                      const unsigned* __restrict__ Wlo,
                                                      const float* __restrict__ bias) {
    extern __shared__ unsigned usm[];
    unsigned* Ash = usm;                          // [2][128][20]
    unsigned* Asl = Ash + 2 * QKV_T_TILE;
    unsigned* Bsh = Asl + 2 * QKV_T_TILE;
    unsigned* Bsl = Bsh + 2 * QKV_T_TILE;

    const int tid = threadIdx.x;
    const int wid = tid >> 5, lane = tid & 31;
    const int warp_m = (wid >> 1) * 32;
    const int warp_n = (wid & 1) * 64;
    const int r = lane >> 2, c = lane & 3;
    const int m0 = blockIdx.y * 128;
    const int n0 = blockIdx.x * 128;

    const int rr0 = tid >> 2;
    const int rr1 = rr0 + 64;
    const int cc = (tid & 3) << 2;

    float acc[2][8][4];
#pragma unroll
    for (int t = 0; t < 2; t++)
#pragma unroll
        for (int u = 0; u < 8; u++)
#pragma unroll
            for (int v = 0; v < 4; v++) acc[t][u][v] = 0.0f;

#pragma unroll
    for (int q = 0; q < 2; q++) {
        int rr = q ? rr1 : rr0;
        size_t aoff = (size_t)(m0 + rr) * D_DIM + cc;
        size_t woff = (size_t)(n0 + rr) * D_DIM + cc;
        cp_async16(&Ash[rr * QKV_T_STRIDE + cc], Ahi_g + aoff);
        cp_async16(&Asl[rr * QKV_T_STRIDE + cc], Alo_g + aoff);
        cp_async16(&Bsh[rr * QKV_T_STRIDE + cc], Whi + woff);
        cp_async16(&Bsl[rr * QKV_T_STRIDE + cc], Wlo + woff);
    }
    CP_COMMIT();

    for (int kt = 0; kt < 48; kt++) {
        const int b = kt & 1;
        CP_WAIT0();
        __syncthreads();

        if (kt < 47) {
            const int k0n = (kt + 1) * 16;
            const int bo = (b ^ 1) * QKV_T_TILE;
#pragma unroll
            for (int q = 0; q < 2; q++) {
                int rr = q ? rr1 : rr0;
                size_t aoff = (size_t)(m0 + rr) * D_DIM + k0n + cc;
                size_t woff = (size_t)(n0 + rr) * D_DIM + k0n + cc;
                cp_async16(&Ash[bo + rr * QKV_T_STRIDE + cc], Ahi_g + aoff);
                cp_async16(&Asl[bo + rr * QKV_T_STRIDE + cc], Alo_g + aoff);
                cp_async16(&Bsh[bo + rr * QKV_T_STRIDE + cc], Whi + woff);
                cp_async16(&Bsl[bo + rr * QKV_T_STRIDE + cc], Wlo + woff);
            }
            CP_COMMIT();
        }

        const unsigned* Ahb = Ash + b * QKV_T_TILE;
        const unsigned* Alb = Asl + b * QKV_T_TILE;
        const unsigned* Bhb = Bsh + b * QKV_T_TILE;
        const unsigned* Blb = Bsl + b * QKV_T_TILE;
#pragma unroll
        for (int k8 = 0; k8 < 16; k8 += 8) {
            unsigned Ahi[2][4], Alo[2][4];
#pragma unroll
            for (int t = 0; t < 2; t++) {
                int m = warp_m + t * 16 + r;
                Ahi[t][0] = Ahb[m * QKV_T_STRIDE + k8 + c];
                Ahi[t][1] = Ahb[(m + 8) * QKV_T_STRIDE + k8 + c];
                Ahi[t][2] = Ahb[m * QKV_T_STRIDE + k8 + c + 4];
                Ahi[t][3] = Ahb[(m + 8) * QKV_T_STRIDE + k8 + c + 4];
                Alo[t][0] = Alb[m * QKV_T_STRIDE + k8 + c];
                Alo[t][1] = Alb[(m + 8) * QKV_T_STRIDE + k8 + c];
                Alo[t][2] = Alb[m * QKV_T_STRIDE + k8 + c + 4];
                Alo[t][3] = Alb[(m + 8) * QKV_T_STRIDE + k8 + c + 4];
            }
#pragma unroll
            for (int u = 0; u < 8; u++) {
                int n = warp_n + u * 8 + r;
                unsigned Bh[2], Bl[2];
                Bh[0] = Bhb[n * QKV_T_STRIDE + k8 + c];
                Bh[1] = Bhb[n * QKV_T_STRIDE + k8 + 4 + c];
                Bl[0] = Blb[n * QKV_T_STRIDE + k8 + c];
                Bl[1] = Blb[n * QKV_T_STRIDE + k8 + 4 + c];
#pragma unroll
                for (int t = 0; t < 2; t++) {
                    mma_tf32(acc[t][u], Ahi[t], Bh);
                    mma_tf32(acc[t][u], Ahi[t], Bl);
                    mma_tf32(acc[t][u], Alo[t], Bh);
                }
            }
        }
    }

#pragma unroll
    for (int t = 0; t < 2; t++) {
        int row0 = m0 + warp_m + t * 16 + r;
#pragma unroll
        for (int u = 0; u < 8; u++) {
            int col = n0 + warp_n + u * 8 + c * 2;
            float2 bz = *(const float2*)(bias + col);
            float2 v0, v1;
            v0.x = acc[t][u][0] + bz.x; v0.y = acc[t][u][1] + bz.y;
            v1.x = acc[t][u][2] + bz.x; v1.y = acc[t][u][3] + bz.y;
            *(float2*)(g_proj + (size_t)row0 * TD_DIM + col) = v0;
            *(float2*)(g_proj + (size_t)(row0 + 8) * TD_DIM + col) = v1;
        }
    }
}

// ---------------- K3a: zero scores + row mask sums ----------------
__global__ __launch_bounds__(256) void scores_zero_kernel(const float* __restrict__ mask) {
    size_t idx = (size_t)blockIdx.x * 1024 + threadIdx.x * 4;
    if (idx < (size_t)H_DIM * L_DIM * L_DIM) {
        float4 z = {0.f, 0.f, 0.f, 0.f};
        *(float4*)(g_scores + idx) = z;
    }
    int t = blockIdx.x * 256 + threadIdx.x;
    if (t < H_DIM * L_DIM) {
        int h = t / L_DIM, j = t % L_DIM;
        float s = 0.0f;
        for (int e = 0; e < E_DIM; e++) s += mask[((size_t)h * E_DIM + e) * L_DIM + j];
        g_rowmask[t] = s;
    }
}

// ---------------- K3b: row scores (3xTF32, e-split 16) ---------------------------
// grid: (4 [2x2 ij-tiles], H, 16 [e-split]); K per block = 8e * 64c = 512.
__global__ __launch_bounds__(256, 2) void row_scores_tc() {
    __shared__ unsigned As_h[16][136], As_l[16][136];
    __shared__ unsigned Bs_h[16][136], Bs_l[16][136];
    const int tid = threadIdx.x;
    const int wid = tid >> 5, lane = tid & 31;
    const int warp_m = (wid >> 1) * 32;
    const int warp_n = (wid & 1) * 64;
    const int r = lane >> 2, c = lane & 3;
    const int it = (blockIdx.x >> 1) * 128;
    const int jt = (blockIdx.x & 1) * 128;
    const int h = blockIdx.y;
    const int e0 = blockIdx.z * 8;

    float acc[2][8][4];
#pragma unroll
    for (int t = 0; t < 2; t++)
#pragma unroll
        for (int u = 0; u < 8; u++)
#pragma unroll
            for (int v = 0; v < 4; v++) acc[t][u][v] = 0.0f;

    for (int e = e0; e < e0 + 8; e++) {
        const float* qbase = g_proj + (size_t)(e * L_DIM) * TD_DIM + h * DH_DIM;
        const float* kbase = qbase + D_DIM;
        for (int k0 = 0; k0 < DH_DIM; k0 += 16) {
#pragma unroll
            for (int q = 0; q < 2; q++) {
                int id = q * 256 + tid;
                int rr = id >> 2;
                int c4 = (id & 3) << 2;
                float4 va = *(const float4*)(qbase + (size_t)(it + rr) * TD_DIM + k0 + c4);
                unsigned hh;
                hh = f2tf32(va.x); As_h[c4 + 0][rr] = hh; As_l[c4 + 0][rr] = f2tf32(va.x - __uint_as_float(hh));
                hh = f2tf32(va.y); As_h[c4 + 1][rr] = hh; As_l[c4 + 1][rr] = f2tf32(va.y - __uint_as_float(hh));
                hh = f2tf32(va.z); As_h[c4 + 2][rr] = hh; As_l[c4 + 2][rr] = f2tf32(va.z - __uint_as_float(hh));
                hh = f2tf32(va.w); As_h[c4 + 3][rr] = hh; As_l[c4 + 3][rr] = f2tf32(va.w - __uint_as_float(hh));
                float4 vb = *(const float4*)(kbase + (size_t)(jt + rr) * TD_DIM + k0 + c4);
                hh = f2tf32(vb.x); Bs_h[c4 + 0][rr] = hh; Bs_l[c4 + 0][rr] = f2tf32(vb.x - __uint_as_float(hh));
                hh = f2tf32(vb.y); Bs_h[c4 + 1][rr] = hh; Bs_l[c4 + 1][rr] = f2tf32(vb.y - __uint_as_float(hh));
                hh = f2tf32(vb.z); Bs_h[c4 + 2][rr] = hh; Bs_l[c4 + 2][rr] = f2tf32(vb.z - __uint_as_float(hh));
                hh = f2tf32(vb.w); Bs_h[c4 + 3][rr] = hh; Bs_l[c4 + 3][rr] = f2tf32(vb.w - __uint_as_float(hh));
            }
            __syncthreads();
#pragma unroll
            for (int k8 = 0; k8 < 16; k8 += 8) {
                unsigned Ah[2][4], Al[2][4];
#pragma unroll
                for (int t = 0; t < 2; t++) {
                    int m = warp_m + t * 16 + r;
                    Ah[t][0] = As_h[k8 + c][m];     Al[t][0] = As_l[k8 + c][m];
                    Ah[t][1] = As_h[k8 + c][m + 8]; Al[t][1] = As_l[k8 + c][m + 8];
                    Ah[t][2] = As_h[k8 + c + 4][m];     Al[t][2] = As_l[k8 + c + 4][m];
                    Ah[t][3] = As_h[k8 + c + 4][m + 8]; Al[t][3] = As_l[k8 + c + 4][m + 8];
                }
#pragma unroll
                for (int u = 0; u < 8; u++) {
                    int n = warp_n + u * 8 + r;
                    unsigned Bh[2], Bl[2];
                    Bh[0] = Bs_h[k8 + c][n];     Bl[0] = Bs_l[k8 + c][n];
                    Bh[1] = Bs_h[k8 + 4 + c][n]; Bl[1] = Bs_l[k8 + 4 + c][n];
#pragma unroll
                    for (int t = 0; t < 2; t++) {
                        mma_tf32(acc[t][u], Ah[t], Bh);
                        mma_tf32(acc[t][u], Ah[t], Bl);
                        mma_tf32(acc[t][u], Al[t], Bh);
                    }
                }
            }
            __syncthreads();
        }
    }

#pragma unroll
    for (int t = 0; t < 2; t++) {
        int row = it + warp_m + t * 16 + r;
#pragma unroll
        for (int u = 0; u < 8; u++) {
            int col = jt + warp_n + u * 8 + c * 2;
            float* p0 = &g_scores[((size_t)h * L_DIM + row) * L_DIM + col];
            atomicAdd(p0, acc[t][u][0]);
            atomicAdd(p0 + 1, acc[t][u][1]);
            float* p1 = &g_scores[((size_t)h * L_DIM + row + 8) * L_DIM + col];
            atomicAdd(p1, acc[t][u][2]);
            atomicAdd(p1 + 1, acc[t][u][3]);
        }
    }
}

// ---------------- K4: softmax over j (adds row mask on the fly) ----------------
__global__ __launch_bounds__(256) void row_softmax_kernel() {
    __shared__ float red[8];
    int h = blockIdx.x / L_DIM;
    float* row = g_scores + (size_t)blockIdx.x * L_DIM;
    float v = row[threadIdx.x] + g_rowmask[h * L_DIM + threadIdx.x];
    float m = block_max256(v, red);
    float p = __expf(v - m);
    float s = block_sum256(p, red);
    row[threadIdx.x] = p / s;
}

// ---------------- K5: row AV + residual (3xTF32) -------------------
__global__ __launch_bounds__(256) void row_av_tc(const float* __restrict__ x,
                                                 float* __restrict__ out) {
    __shared__ float As[16][136];   // P^T: [j][i]
    __shared__ float Bs[16][68];    // V:   [j][c]
    const int tid = threadIdx.x;
    const int wid = tid >> 5, lane = tid & 31;
    const int warp_m = (wid >> 1) * 32;
    const int warp_n = (wid & 1) * 32;
    const int r = lane >> 2, c = lane & 3;
    const int it = blockIdx.x * 128;
    const int h = blockIdx.y;
    const int e = blockIdx.z;

    const float* pbase = g_scores + (size_t)h * L_DIM * L_DIM;
    const float* vbase = g_proj + (size_t)(e * L_DIM) * TD_DIM + 2 * D_DIM + h * DH_DIM;

    const int rr0 = tid >> 2, rr1 = rr0 + 64;
    const int cc = (tid & 3) << 2;
    const int vj = tid >> 4;
    const int vc = (tid & 15) << 2;

    float acc[2][4][4];
#pragma unroll
    for (int t = 0; t < 2; t++)
#pragma unroll
        for (int u = 0; u < 4; u++)
#pragma unroll
            for (int v = 0; v < 4; v++) acc[t][u][v] = 0.0f;

    for (int kt = 0; kt < 16; kt++) {
        const int j0 = kt * 16;
#pragma unroll
        for (int q = 0; q < 2; q++) {
            int rr = q ? rr1 : rr0;
            float4 p = *(const float4*)(pbase + (size_t)(it + rr) * L_DIM + j0 + cc);
            As[cc + 0][rr] = p.x; As[cc + 1][rr] = p.y;
            As[cc + 2][rr] = p.z; As[cc + 3][rr] = p.w;
        }
        {
            float4 v = *(const float4*)(vbase + (size_t)(j0 + vj) * TD_DIM + vc);
            *(float4*)&Bs[vj][vc] = v;
        }
        __syncthreads();
#pragma unroll
        for (int k8 = 0; k8 < 16; k8 += 8) {
            unsigned Ahi[2][4], Alo[2][4];
#pragma unroll
            for (int t = 0; t < 2; t++) {
                int m = warp_m + t * 16 + r;
                split3(As[k8 + c][m],     Ahi[t][0], Alo[t][0]);
                split3(As[k8 + c][m + 8], Ahi[t][1], Alo[t][1]);
                split3(As[k8 + c + 4][m],     Ahi[t][2], Alo[t][2]);
                split3(As[k8 + c + 4][m + 8], Ahi[t][3], Alo[t][3]);
            }
#pragma unroll
            for (int u = 0; u < 4; u++) {
                int n = warp_n + u * 8 + r;
                unsigned Bh[2], Bl[2];
                split3(Bs[k8 + c][n],     Bh[0], Bl[0]);
                split3(Bs[k8 + 4 + c][n], Bh[1], Bl[1]);
#pragma unroll
                for (int t = 0; t < 2; t++) {
                    mma_tf32(acc[t][u], Ahi[t], Bh);
                    mma_tf32(acc[t][u], Ahi[t], Bl);
                    mma_tf32(acc[t][u], Alo[t], Bh);
                }
            }
        }
        __syncthreads();
    }

#pragma unroll
    for (int t = 0; t < 2; t++) {
        int row = it + warp_m + t * 16 + r;
#pragma unroll
        for (int u = 0; u < 4; u++) {
            int col = warp_n + u * 8 + c * 2;
            size_t off0 = ((size_t)(e * L_DIM + row)) * D_DIM + h * DH_DIM + col;
            size_t off1 = ((size_t)(e * L_DIM + row + 8)) * D_DIM + h * DH_DIM + col;
            float2 x0 = *(const float2*)(x + off0);
            float2 x1 = *(const float2*)(x + off1);
            float2 v0, v1;
            v0.x = x0.x + acc[t][u][0]; v0.y = x0.y + acc[t][u][1];
            v1.x = x1.x + acc[t][u][2]; v1.y = x1.y + acc[t][u][3];
            *(float2*)(out + off0) = v0;
            *(float2*)(out + off1) = v1;
        }
    }
}

// ---------------- K8: fused column attention (3xTF32), one block per (h,l) ----
#define CK_STR 136
#define CV_STR 72
#define COL_SMEM_FLOATS (64 * CK_STR + 128 * CV_STR + 128 * CK_STR + 256)
__global__ __launch_bounds__(256) void col_attn_tc(const float* __restrict__ mask,
                                                   float* __restrict__ out) {
    extern __shared__ float sm[];
    float* Ks = sm;                         // [c][j] stride CK_STR
    float* Vs = Ks + 64 * CK_STR;           // [j][c] stride CV_STR
    float* Ss = Vs + 128 * CV_STR;          // [j][i] stride CK_STR
    float* red2 = Ss + 128 * CK_STR;
    float* Qs = Ss;                         // [c][i] alias (first 64 rows)
    const int tid = threadIdx.x;
    const int wid = tid >> 5, lane = tid & 31;
    const int r = lane >> 2, c = lane & 3;
    const int l = blockIdx.x;
    const int h = blockIdx.y;

    const float* qbase = g_proj + (size_t)l * TD_DIM + h * DH_DIM;
    const float* kbase = qbase + D_DIM;
    const float* vbase = qbase + 2 * D_DIM;

#pragma unroll
    for (int q = 0; q < 8; q++) {
        int id = q * 256 + tid;
        int rr = id & 127;
        int c4 = ((id >> 7) & 15) << 2;
        float4 va = *(const float4*)(qbase + (size_t)rr * L_DIM * TD_DIM + c4);
        Qs[(c4 + 0) * CK_STR + rr] = va.x; Qs[(c4 + 1) * CK_STR + rr] = va.y;
        Qs[(c4 + 2) * CK_STR + rr] = va.z; Qs[(c4 + 3) * CK_STR + rr] = va.w;
        float4 vb = *(const float4*)(kbase + (size_t)rr * L_DIM * TD_DIM + c4);
        Ks[(c4 + 0) * CK_STR + rr] = vb.x; Ks[(c4 + 1) * CK_STR + rr] = vb.y;
        Ks[(c4 + 2) * CK_STR + rr] = vb.z; Ks[(c4 + 3) * CK_STR + rr] = vb.w;
        int rJ = id >> 4;
        int c42 = (id & 15) << 2;
        *(float4*)&Vs[rJ * CV_STR + c42] = *(const float4*)(vbase + (size_t)rJ * L_DIM * TD_DIM + c42);
    }
    __syncthreads();

    float accS[2][8][4];
    {
        const int warp_m = (wid >> 1) * 32;
        const int warp_n = (wid & 1) * 64;
#pragma unroll
        for (int t = 0; t < 2; t++)
#pragma unroll
            for (int u = 0; u < 8; u++)
#pragma unroll
                for (int v = 0; v < 4; v++) accS[t][u][v] = 0.0f;
#pragma unroll
        for (int k8 = 0; k8 < 64; k8 += 8) {
            unsigned Ahi[2][4], Alo[2][4];
#pragma unroll
            for (int t = 0; t < 2; t++) {
                int m = warp_m + t * 16 + r;
                split3(Qs[(k8 + c) * CK_STR + m],     Ahi[t][0], Alo[t][0]);
                split3(Qs[(k8 + c) * CK_STR + m + 8], Ahi[t][1], Alo[t][1]);
                split3(Qs[(k8 + c + 4) * CK_STR + m],     Ahi[t][2], Alo[t][2]);
                split3(Qs[(k8 + c + 4) * CK_STR + m + 8], Ahi[t][3], Alo[t][3]);
            }
#pragma unroll
            for (int u = 0; u < 8; u++) {
                int n = warp_n + u * 8 + r;
                unsigned Bh[2], Bl[2];
                split3(Ks[(k8 + c) * CK_STR + n],     Bh[0], Bl[0]);
                split3(Ks[(k8 + 4 + c) * CK_STR + n], Bh[1], Bl[1]);
#pragma unroll
                for (int t = 0; t < 2; t++) {
                    mma_tf32(accS[t][u], Ahi[t], Bh);
                    mma_tf32(accS[t][u], Ahi[t], Bl);
                    mma_tf32(accS[t][u], Alo[t], Bh);
                }
            }
        }
    }
    __syncthreads();

    {
        const int warp_m = (wid >> 1) * 32;
        const int warp_n = (wid & 1) * 64;
#pragma unroll
        for (int t = 0; t < 2; t++) {
            int m = warp_m + t * 16 + r;
#pragma unroll
            for (int u = 0; u < 8; u++) {
                int j0 = warp_n + u * 8 + c * 2;
                float mk0 = mask[((size_t)h * E_DIM + j0) * L_DIM + l];
                float mk1 = mask[((size_t)h * E_DIM + j0 + 1) * L_DIM + l];
                Ss[j0 * CK_STR + m]           = accS[t][u][0] + mk0;
                Ss[(j0 + 1) * CK_STR + m]     = accS[t][u][1] + mk1;
                Ss[j0 * CK_STR + m + 8]       = accS[t][u][2] + mk0;
                Ss[(j0 + 1) * CK_STR + m + 8] = accS[t][u][3] + mk1;
            }
        }
    }
    __syncthreads();

    {
        const int i = tid & 127;
        const int half = tid >> 7;
        const int j0 = half * 64;
        float m = -3.4e38f;
#pragma unroll 8
        for (int j = 0; j < 64; j++) m = fmaxf(m, Ss[(j0 + j) * CK_STR + i]);
        red2[tid] = m;
        __syncthreads();
        m = fmaxf(red2[i], red2[i + 128]);
        float s = 0.0f;
#pragma unroll 8
        for (int j = 0; j < 64; j++) {
            float p = __expf(Ss[(j0 + j) * CK_STR + i] - m);
            Ss[(j0 + j) * CK_STR + i] = p;
            s += p;
        }
        __syncthreads();
        red2[tid] = s;
        __syncthreads();
        float inv = 1.0f / (red2[i] + red2[i + 128]);
#pragma unroll 8
        for (int j = 0; j < 64; j++) Ss[(j0 + j) * CK_STR + i] *= inv;
    }
    __syncthreads();

    {
        const int warp_m = (wid >> 1) * 32;
        const int warp_n = (wid & 1) * 32;
        float accO[2][4][4];
#pragma unroll
        for (int t = 0; t < 2; t++)
#pragma unroll
            for (int u = 0; u < 4; u++)
#pragma unroll
                for (int v = 0; v < 4; v++) accO[t][u][v] = 0.0f;
#pragma unroll
        for (int k8 = 0; k8 < 128; k8 += 8) {
            unsigned Ahi[2][4], Alo[2][4];
#pragma unroll
            for (int t = 0; t < 2; t++) {
                int m = warp_m + t * 16 + r;
                split3(Ss[(k8 + c) * CK_STR + m],     Ahi[t][0], Alo[t][0]);
                split3(Ss[(k8 + c) * CK_STR + m + 8], Ahi[t][1], Alo[t][1]);
                split3(Ss[(k8 + c + 4) * CK_STR + m],     Ahi[t][2], Alo[t][2]);
                split3(Ss[(k8 + c + 4) * CK_STR + m + 8], Ahi[t][3], Alo[t][3]);
            }
#pragma unroll
            for (int u = 0; u < 4; u++) {
                int n = warp_n + u * 8 + r;
                unsigned Bh[2], Bl[2];
                split3(Vs[(k8 + c) * CV_STR + n],     Bh[0], Bl[0]);
                split3(Vs[(k8 + 4 + c) * CV_STR + n], Bh[1], Bl[1]);
#pragma unroll
                for (int t = 0; t < 2; t++) {
                    mma_tf32(accO[t][u], Ahi[t], Bh);
                    mma_tf32(accO[t][u], Ahi[t], Bl);
                    mma_tf32(accO[t][u], Alo[t], Bh);
                }
            }
        }

#pragma unroll
        for (int t = 0; t < 2; t++) {
            int row = warp_m + t * 16 + r;
#pragma unroll
            for (int u = 0; u < 4; u++) {
                int col = warp_n + u * 8 + c * 2;
                size_t off0 = ((size_t)row * L_DIM + l) * D_DIM + h * DH_DIM + col;
                size_t off1 = ((size_t)(row + 8) * L_DIM + l) * D_DIM + h * DH_DIM + col;
                float2 c0 = *(const float2*)(out + off0);
                float2 c1 = *(const float2*)(out + off1);
                c0.x += accO[t][u][0]; c0.y += accO[t][u][1];
                c1.x += accO[t][u][2]; c1.y += accO[t][u][3];
                *(float2*)(out + off0) = c0;
                *(float2*)(out + off1) = c1;
            }
        }
    }
}

// ---------------- launcher ----------------
extern "C" void kernel_launch(void* const* d_in, const int* in_sizes, int n_in,
                              void* d_out, int out_size) {
    const float* x     = (const float*)d_in[0];
    const float* mask  = (const float*)d_in[1];
    const float* w_row = (const float*)d_in[2];
    const float* b_row = (const float*)d_in[3];
    const float* w_col = (const float*)d_in[4];
    const float* b_col = (const float*)d_in[5];
    const float* g1    = (const float*)d_in[6];
    const float* be1   = (const float*)d_in[7];
    const float* g2    = (const float*)d_in[8];
    const float* be2   = (const float*)d_in[9];
    float* out = (float*)d_out;

    unsigned *wr_hi, *wr_lo, *wc_hi, *wc_lo, *xh, *xl;
    cudaGetSymbolAddress((void**)&wr_hi, g_wr_hi);
    cudaGetSymbolAddress((void**)&wr_lo, g_wr_lo);
    cudaGetSymbolAddress((void**)&wc_hi, g_wc_hi);
    cudaGetSymbolAddress((void**)&wc_lo, g_wc_lo);
    cudaGetSymbolAddress((void**)&xh, g_xh);
    cudaGetSymbolAddress((void**)&xl, g_xl);

    const int col_smem = COL_SMEM_FLOATS * (int)sizeof(float);   // ~142 KB
    cudaFuncSetAttribute(col_attn_tc, cudaFuncAttributeMaxDynamicSharedMemorySize, col_smem);
    cudaFuncSetAttribute(qkv_gemm_tc, cudaFuncAttributeMaxDynamicSharedMemorySize, QKV_SMEM_BYTES);

    const int wsplit_blocks = (TD_DIM * D_DIM) / (256 * 4);   // 1728

    // ---- row attention stage ----
    split_w_kernel<<<wsplit_blocks, 256>>>(w_row, wr_hi, wr_lo);
    split_w_kernel<<<wsplit_blocks, 256>>>(w_col, wc_hi, wc_lo);
    ln_split_kernel<<<N_ROWS, 256>>>(x, g1, be1);
    qkv_gemm_tc<<<dim3(TD_DIM / 128, N_ROWS / 128), 256, QKV_SMEM_BYTES>>>(xh, xl, wr_hi, wr_lo, b_row);
    scores_zero_kernel<<<(H_DIM * L_DIM * L_DIM) / 1024, 256>>>(mask);
    row_scores_tc<<<dim3(4, H_DIM, 16), 256>>>();
    row_softmax_kernel<<<H_DIM * L_DIM, 256>>>();
    row_av_tc<<<dim3(2, H_DIM, E_DIM), 256>>>(x, out);   // out = x + row_out

    // ---- column attention stage ----
    ln_split_kernel<<<N_ROWS, 256>>>(out, g2, be2);
    qkv_gemm_tc<<<dim3(TD_DIM / 128, N_ROWS / 128), 256, QKV_SMEM_BYTES>>>(xh, xl, wc_hi, wc_lo, b_col);
    col_attn_tc<<<dim3(L_DIM, H_DIM), 256, col_smem>>>(mask, out);  // out += col_out
}